// round 1
// baseline (speedup 1.0000x reference)
#include <cuda_runtime.h>

// Problem constants (fixed by setup_inputs)
#define B_ 4096
#define L_ 200
#define E_ 128
#define A_ 128
#define TL 32
#define LD1 132   // padded leading dim for h1/h2 tiles (float4-aligned, conflict-light)

// Scratch (device globals: allocation is forbidden)
__device__ float g_qw[B_ * A_];      // q @ (W1q + W1d) + b1, per batch row
__device__ float g_Wk[E_ * A_];      // W1k - W1d

// ---------------------------------------------------------------------------
// Prep kernel 1: combined key-weight  Wk[e][a] = W1[E+e][a] - W1[2E+e][a]
// ---------------------------------------------------------------------------
__global__ void prep_wk(const float* __restrict__ W1) {
    int idx = blockIdx.x * blockDim.x + threadIdx.x;
    if (idx < E_ * A_) {
        int e = idx / A_, a = idx % A_;
        g_Wk[idx] = W1[(E_ + e) * A_ + a] - W1[(2 * E_ + e) * A_ + a];
    }
}

// ---------------------------------------------------------------------------
// Prep kernel 2: qw[b][a] = b1[a] + sum_e q[b][e] * (W1[e][a] + W1[2E+e][a])
// One block per batch row, 128 threads (one per a).
// ---------------------------------------------------------------------------
__global__ void prep_qw(const float* __restrict__ query,
                        const float* __restrict__ W1,
                        const float* __restrict__ b1) {
    __shared__ float qs[E_];
    int b = blockIdx.x;
    int a = threadIdx.x;
    qs[a] = query[(size_t)b * E_ + a];
    __syncthreads();
    float acc = b1[a];
#pragma unroll 4
    for (int e = 0; e < E_; e++) {
        acc = fmaf(qs[e], W1[e * A_ + a] + W1[(2 * E_ + e) * A_ + a], acc);
    }
    g_qw[(size_t)b * A_ + a] = acc;
}

// ---------------------------------------------------------------------------
// Main fused kernel: one CTA per batch row. L tiled by TL with online softmax.
// ---------------------------------------------------------------------------
struct SmemT {
    float Wk[E_ * A_];        // 64 KB
    float Wm[E_ * A_];        // 64 KB
    float kp[TL * E_];        // 16 KB   keys + pos tile
    float h1[TL * LD1];       // 16.5 KB
    float h2[TL * LD1];       // 16.5 KB
    float qv[E_];
    float qw[A_];
    float b2v[A_];
    float w3v[A_];
    float scores[TL];
    float wts[TL];
    float Ovec[E_];
    float alpha;
    float Ssum;
};

__global__ __launch_bounds__(256, 1) void din_main(
    const float* __restrict__ query,
    const float* __restrict__ keys,
    const void*  __restrict__ len_ptr,
    const float* __restrict__ pos,
    const float* __restrict__ W1,
    const float* __restrict__ W2,
    const float* __restrict__ b2,
    const float* __restrict__ W3,
    const float* __restrict__ b3,
    float* __restrict__ out)
{
    extern __shared__ char smem_raw[];
    SmemT& s = *reinterpret_cast<SmemT*>(smem_raw);
    const int b = blockIdx.x;
    const int tid = threadIdx.x;

    // ---- keys_length: robust int64/int32 detection (values are in [1, L]) ----
    // int64 layout: first 8 bytes = small value. int32 layout: two packed
    // lengths -> >= 2^32 as u64. Deterministic, same result on every call.
    unsigned long long first8 = *(const unsigned long long*)len_ptr;
    int len;
    if (first8 <= (unsigned long long)L_) {
        len = (int)((const long long*)len_ptr)[b];
    } else {
        len = ((const int*)len_ptr)[b];
    }

    // ---- stage weights / vectors into shared ----
    {
        const float4* Wk_g = (const float4*)g_Wk;
        const float4* Wm_g = (const float4*)(W1 + 3 * E_ * A_);
        float4* Wk_s = (float4*)s.Wk;
        float4* Wm_s = (float4*)s.Wm;
        for (int i = tid; i < E_ * A_ / 4; i += 256) {
            Wk_s[i] = Wk_g[i];
            Wm_s[i] = Wm_g[i];
        }
    }
    if (tid < E_) {
        s.qv[tid]  = query[(size_t)b * E_ + tid];
        s.qw[tid]  = g_qw[(size_t)b * A_ + tid];
        s.b2v[tid] = b2[tid];
        s.w3v[tid] = W3[tid];
        s.Ovec[tid] = 0.f;
    }
    __syncthreads();

    const float b3v = b3[0];
    float Mv = -1e30f;   // running max (meaningful in warp 0)
    float Sv = 0.f;      // running sum (meaningful in warp 0)

    const int lg = tid >> 5;      // 0..7  -> l block of 4
    const int ag = tid & 31;      // 0..31 -> a block of 4
    const int lb = lg * 4;
    const int a0 = ag * 4;

    for (int l0 = 0; l0 < L_; l0 += TL) {
        const int tlc = min(TL, L_ - l0);

        // ---- load kp tile = keys + pos (zero-pad tail rows) ----
        for (int i = tid; i < TL * E_ / 4; i += 256) {
            int l = i >> 5;      // 32 float4 per row
            int c = i & 31;
            float4 r;
            if (l < tlc) {
                float4 kv = ((const float4*)keys)[((size_t)b * L_ + l0 + l) * (E_ / 4) + c];
                float4 pv = ((const float4*)pos)[(size_t)(l0 + l) * (E_ / 4) + c];
                r.x = kv.x + pv.x; r.y = kv.y + pv.y;
                r.z = kv.z + pv.z; r.w = kv.w + pv.w;
            } else {
                r = make_float4(0.f, 0.f, 0.f, 0.f);
            }
            ((float4*)s.kp)[i] = r;
        }
        __syncthreads();

        // ---- GEMM1: h1 = relu(qw + kp@Wk + (q*kp)@Wm) ----
        {
            float acc[4][4];
#pragma unroll
            for (int i = 0; i < 4; i++)
#pragma unroll
                for (int j = 0; j < 4; j++) acc[i][j] = 0.f;

            const float* kpr = &s.kp[lb * E_];
#pragma unroll 2
            for (int e = 0; e < E_; e++) {
                float qe = s.qv[e];
                float4 wk = *(const float4*)&s.Wk[e * A_ + a0];
                float4 wm = *(const float4*)&s.Wm[e * A_ + a0];
#pragma unroll
                for (int i = 0; i < 4; i++) {
                    float kv = kpr[i * E_ + e];
                    float mv = kv * qe;
                    acc[i][0] = fmaf(kv, wk.x, acc[i][0]);
                    acc[i][1] = fmaf(kv, wk.y, acc[i][1]);
                    acc[i][2] = fmaf(kv, wk.z, acc[i][2]);
                    acc[i][3] = fmaf(kv, wk.w, acc[i][3]);
                    acc[i][0] = fmaf(mv, wm.x, acc[i][0]);
                    acc[i][1] = fmaf(mv, wm.y, acc[i][1]);
                    acc[i][2] = fmaf(mv, wm.z, acc[i][2]);
                    acc[i][3] = fmaf(mv, wm.w, acc[i][3]);
                }
            }
            float4 qwv = *(const float4*)&s.qw[a0];
#pragma unroll
            for (int i = 0; i < 4; i++) {
                float4 r;
                r.x = fmaxf(acc[i][0] + qwv.x, 0.f);
                r.y = fmaxf(acc[i][1] + qwv.y, 0.f);
                r.z = fmaxf(acc[i][2] + qwv.z, 0.f);
                r.w = fmaxf(acc[i][3] + qwv.w, 0.f);
                *(float4*)&s.h1[(lb + i) * LD1 + a0] = r;
            }
        }
        __syncthreads();

        // ---- GEMM2: h2 = relu(h1 @ W2 + b2), W2 streamed via L1/L2 ----
        {
            float acc[4][4];
#pragma unroll
            for (int i = 0; i < 4; i++)
#pragma unroll
                for (int j = 0; j < 4; j++) acc[i][j] = 0.f;

            const float4* W2g = (const float4*)W2;
#pragma unroll 2
            for (int k = 0; k < A_; k++) {
                float4 w2 = __ldg(&W2g[k * (A_ / 4) + ag]);
#pragma unroll
                for (int i = 0; i < 4; i++) {
                    float hv = s.h1[(lb + i) * LD1 + k];
                    acc[i][0] = fmaf(hv, w2.x, acc[i][0]);
                    acc[i][1] = fmaf(hv, w2.y, acc[i][1]);
                    acc[i][2] = fmaf(hv, w2.z, acc[i][2]);
                    acc[i][3] = fmaf(hv, w2.w, acc[i][3]);
                }
            }
            float4 b2v = *(const float4*)&s.b2v[a0];
#pragma unroll
            for (int i = 0; i < 4; i++) {
                float4 r;
                r.x = fmaxf(acc[i][0] + b2v.x, 0.f);
                r.y = fmaxf(acc[i][1] + b2v.y, 0.f);
                r.z = fmaxf(acc[i][2] + b2v.z, 0.f);
                r.w = fmaxf(acc[i][3] + b2v.w, 0.f);
                *(float4*)&s.h2[(lb + i) * LD1 + a0] = r;
            }
        }
        __syncthreads();

        // ---- scores: s[l] = b3 + h2[l] . W3   (8 threads per l) ----
        {
            int lw = tid >> 3;      // 0..31
            int t8 = tid & 7;
            float p = 0.f;
            int abase = t8 * 16;
#pragma unroll
            for (int a = 0; a < 16; a++)
                p = fmaf(s.h2[lw * LD1 + abase + a], s.w3v[abase + a], p);
#pragma unroll
            for (int off = 4; off >= 1; off >>= 1)
                p += __shfl_xor_sync(0xffffffffu, p, off);
            if (t8 == 0) s.scores[lw] = p + b3v;
        }
        __syncthreads();

        // ---- online softmax update (warp 0) ----
        if (tid < 32) {
            int l = tid;
            bool valid = (l < tlc) && ((l0 + l) < len);
            float sc = valid ? s.scores[l] : -1e30f;
            float tmax = sc;
#pragma unroll
            for (int off = 16; off >= 1; off >>= 1)
                tmax = fmaxf(tmax, __shfl_xor_sync(0xffffffffu, tmax, off));
            float newM = fmaxf(Mv, tmax);
            float w = valid ? __expf(sc - newM) : 0.f;
            float wsum = w;
#pragma unroll
            for (int off = 16; off >= 1; off >>= 1)
                wsum += __shfl_xor_sync(0xffffffffu, wsum, off);
            float al = __expf(Mv - newM);   // 0 on first tile (Mv = -1e30)
            Sv = Sv * al + wsum;
            Mv = newM;
            s.wts[l] = w;
            if (l == 0) s.alpha = al;
        }
        __syncthreads();

        // ---- accumulate O[e] = O[e]*alpha + sum_l w[l]*kp[l][e] ----
        if (tid < E_) {
            float Ov = s.Ovec[tid] * s.alpha;
#pragma unroll 4
            for (int l = 0; l < tlc; l++)
                Ov = fmaf(s.wts[l], s.kp[l * E_ + tid], Ov);
            s.Ovec[tid] = Ov;
        }
        __syncthreads();
    }

    if (tid == 0) s.Ssum = Sv;
    __syncthreads();
    if (tid < E_) out[(size_t)b * E_ + tid] = s.Ovec[tid] / s.Ssum;
}

// ---------------------------------------------------------------------------
// Entry point
// ---------------------------------------------------------------------------
extern "C" void kernel_launch(void* const* d_in, const int* in_sizes, int n_in,
                              void* d_out, int out_size) {
    const float* query = (const float*)d_in[0];
    const float* keys  = (const float*)d_in[1];
    const void*  klen  = d_in[2];
    const float* pos   = (const float*)d_in[3];
    const float* W1    = (const float*)d_in[4];
    const float* b1    = (const float*)d_in[5];
    const float* W2    = (const float*)d_in[6];
    const float* b2    = (const float*)d_in[7];
    const float* W3    = (const float*)d_in[8];
    const float* b3    = (const float*)d_in[9];
    float* out = (float*)d_out;

    (void)in_sizes; (void)n_in; (void)out_size;

    size_t smem = sizeof(SmemT);
    cudaFuncSetAttribute(din_main, cudaFuncAttributeMaxDynamicSharedMemorySize,
                         (int)smem);

    prep_wk<<<(E_ * A_ + 255) / 256, 256>>>(W1);
    prep_qw<<<B_, 128>>>(query, W1, b1);
    din_main<<<B_, 256, smem>>>(query, keys, klen, pos, W1, W2, b2, W3, b3, out);
}

// round 3
// speedup vs baseline: 4.5248x; 4.5248x over previous
#include <cuda_runtime.h>
#include <cstdint>

#define B_ 4096
#define L_ 200
#define E_ 128
#define A_ 128
#define MR 256          // L padded to 256 rows (8 warps x 32 rows)
#define LDA 132         // padded leading dims (conflict-free: stride mod 32 = 4)
#define LDB 132

// Global scratch (allocation is forbidden)
__device__ float g_qw[B_ * A_];       // q @ (W1q + W1d) + b1
__device__ float g_WkT[A_ * E_];      // (W1k - W1d)^T   [a][e]
__device__ float g_WmT[A_ * E_];      // W1m^T           [a][e]
__device__ float g_W2T[A_ * A_];      // W2^T            [aout][ain]

__device__ __forceinline__ float tf32r(float f) {
    uint32_t u;
    asm("cvt.rna.tf32.f32 %0, %1;" : "=r"(u) : "f"(f));
    return __uint_as_float(u);
}

// D += A(16x8) * B(8x8), tf32 inputs, fp32 accum
#define MMA8(d, a, b0, b1)                                                     \
    asm volatile("mma.sync.aligned.m16n8k8.row.col.f32.tf32.tf32.f32 "         \
                 "{%0,%1,%2,%3}, {%4,%5,%6,%7}, {%8,%9}, {%0,%1,%2,%3};"       \
                 : "+f"((d)[0]), "+f"((d)[1]), "+f"((d)[2]), "+f"((d)[3])      \
                 : "r"((a)[0]), "r"((a)[1]), "r"((a)[2]), "r"((a)[3]),         \
                   "r"(b0), "r"(b1))

// ---------------- prep kernels ----------------
__global__ void prep_wt(const float* __restrict__ W1, const float* __restrict__ W2) {
    int idx = blockIdx.x * blockDim.x + threadIdx.x;
    if (idx < A_ * E_) {
        int a = idx >> 7, e = idx & 127;
        g_WkT[a * E_ + e] = W1[(E_ + e) * A_ + a] - W1[(2 * E_ + e) * A_ + a];
        g_WmT[a * E_ + e] = W1[(3 * E_ + e) * A_ + a];
        g_W2T[a * A_ + e] = W2[e * A_ + a];
    }
}

__global__ void prep_qw(const float* __restrict__ query,
                        const float* __restrict__ W1,
                        const float* __restrict__ b1) {
    __shared__ float qs[E_];
    int b = blockIdx.x, a = threadIdx.x;
    qs[a] = query[(size_t)b * E_ + a];
    __syncthreads();
    float acc = b1[a];
#pragma unroll 4
    for (int e = 0; e < E_; e++)
        acc = fmaf(qs[e], W1[e * A_ + a] + W1[(2 * E_ + e) * A_ + a], acc);
    g_qw[(size_t)b * A_ + a] = acc;
}

// ---------------- main kernel ----------------
struct Misc {
    float qv[E_], qwv[A_], b2v[A_], w3v[A_];
    float scores[MR], wts[MR];
    float red[16], po[256];
};

#define SMEM_FLOATS (MR * LDA + A_ * LDB + sizeof(Misc) / 4)
#define SMEM_TOTAL  ((int)(SMEM_FLOATS * 4))

__global__ __launch_bounds__(256, 1) void din_main(
    const float* __restrict__ query,
    const float* __restrict__ keys,
    const void*  __restrict__ len_ptr,
    const float* __restrict__ pos,
    const float* __restrict__ b2,
    const float* __restrict__ W3,
    const float* __restrict__ b3,
    float* __restrict__ out)
{
    extern __shared__ float sm[];
    float* As = sm;                       // kp tile, later h1   [MR x LDA]
    float* Bs = sm + MR * LDA;            // Wc, later W2T       [A_ x LDB]
    Misc*  m  = (Misc*)(sm + MR * LDA + A_ * LDB);

    const int b = blockIdx.x;
    const int tid = threadIdx.x;
    const int wid = tid >> 5;
    const int lane = tid & 31;
    const int g = lane >> 2;          // group 0..7
    const int tig = lane & 3;         // thread in group
    const int mbase = wid * 32;

    // keys_length dtype sniff (values in [1, L])
    unsigned long long first8 = *(const unsigned long long*)len_ptr;
    int len = (first8 <= (unsigned long long)L_)
            ? (int)((const long long*)len_ptr)[b]
            : ((const int*)len_ptr)[b];

    if (tid < 128) {
        m->qv[tid]  = query[(size_t)b * E_ + tid];
        m->qwv[tid] = g_qw[(size_t)b * A_ + tid];
        m->b2v[tid] = b2[tid];
        m->w3v[tid] = W3[tid];
    }
    __syncthreads();

    // ---- build A = kp (tf32-rounded, zero pad rows >= L), B = Wc = WkT + q*WmT ----
    {
        const float4* k4 = (const float4*)(keys + (size_t)b * L_ * E_);
        const float4* p4 = (const float4*)pos;
        for (int idx = tid; idx < MR * 32; idx += 256) {
            int l = idx >> 5, c4 = idx & 31;
            float4 v = make_float4(0.f, 0.f, 0.f, 0.f);
            if (l < L_) {
                float4 kv = k4[l * 32 + c4], pv = p4[l * 32 + c4];
                v.x = tf32r(kv.x + pv.x); v.y = tf32r(kv.y + pv.y);
                v.z = tf32r(kv.z + pv.z); v.w = tf32r(kv.w + pv.w);
            }
            *(float4*)&As[l * LDA + c4 * 4] = v;
        }
        const float4* wk4 = (const float4*)g_WkT;
        const float4* wm4 = (const float4*)g_WmT;
        for (int idx = tid; idx < 128 * 32; idx += 256) {
            int a = idx >> 5, c4 = idx & 31;
            float4 wk = wk4[a * 32 + c4], wm = wm4[a * 32 + c4];
            float4 qe = *(const float4*)&m->qv[c4 * 4];
            float4 v;
            v.x = tf32r(fmaf(qe.x, wm.x, wk.x));
            v.y = tf32r(fmaf(qe.y, wm.y, wk.y));
            v.z = tf32r(fmaf(qe.z, wm.z, wk.z));
            v.w = tf32r(fmaf(qe.w, wm.w, wk.w));
            *(float4*)&Bs[a * LDB + c4 * 4] = v;
        }
    }
    __syncthreads();

    float acc[2][16][4];

    // ================= GEMM1: h1_raw = kp @ Wc^T =================
#pragma unroll
    for (int mt = 0; mt < 2; mt++)
#pragma unroll
        for (int nt = 0; nt < 16; nt++)
#pragma unroll
            for (int j = 0; j < 4; j++) acc[mt][nt][j] = 0.f;

#pragma unroll 1
    for (int k0 = 0; k0 < 128; k0 += 8) {
        uint32_t a[2][4];
#pragma unroll
        for (int mt = 0; mt < 2; mt++) {
            int r = (mbase + 16 * mt + g) * LDA + k0 + tig;
            a[mt][0] = __float_as_uint(As[r]);
            a[mt][1] = __float_as_uint(As[r + 8 * LDA]);
            a[mt][2] = __float_as_uint(As[r + 4]);
            a[mt][3] = __float_as_uint(As[r + 8 * LDA + 4]);
        }
#pragma unroll
        for (int nt = 0; nt < 16; nt++) {
            int rb = (nt * 8 + g) * LDB + k0 + tig;
            uint32_t b0 = __float_as_uint(Bs[rb]);
            uint32_t b1 = __float_as_uint(Bs[rb + 4]);
            MMA8(acc[0][nt], a[0], b0, b1);
            MMA8(acc[1][nt], a[1], b0, b1);
        }
    }

    // epilogue 1: h1 = relu(acc + qw), tf32-rounded, overwrite own rows of As
#pragma unroll
    for (int mt = 0; mt < 2; mt++) {
        int r0 = mbase + 16 * mt + g;
#pragma unroll
        for (int nt = 0; nt < 16; nt++) {
            int c0 = nt * 8 + 2 * tig;
            float q0 = m->qwv[c0], q1 = m->qwv[c0 + 1];
            float2 v0, v1;
            v0.x = tf32r(fmaxf(acc[mt][nt][0] + q0, 0.f));
            v0.y = tf32r(fmaxf(acc[mt][nt][1] + q1, 0.f));
            v1.x = tf32r(fmaxf(acc[mt][nt][2] + q0, 0.f));
            v1.y = tf32r(fmaxf(acc[mt][nt][3] + q1, 0.f));
            *(float2*)&As[r0 * LDA + c0] = v0;
            *(float2*)&As[(r0 + 8) * LDA + c0] = v1;
        }
    }
    __syncthreads();

    // load W2T (tf32) into Bs
    {
        const float4* w24 = (const float4*)g_W2T;
        for (int idx = tid; idx < 128 * 32; idx += 256) {
            int a = idx >> 5, c4 = idx & 31;
            float4 w = w24[a * 32 + c4];
            w.x = tf32r(w.x); w.y = tf32r(w.y);
            w.z = tf32r(w.z); w.w = tf32r(w.w);
            *(float4*)&Bs[a * LDB + c4 * 4] = w;
        }
    }
    __syncthreads();

    // ================= GEMM2: h2_raw = h1 @ W2 =================
#pragma unroll
    for (int mt = 0; mt < 2; mt++)
#pragma unroll
        for (int nt = 0; nt < 16; nt++)
#pragma unroll
            for (int j = 0; j < 4; j++) acc[mt][nt][j] = 0.f;

#pragma unroll 1
    for (int k0 = 0; k0 < 128; k0 += 8) {
        uint32_t a[2][4];
#pragma unroll
        for (int mt = 0; mt < 2; mt++) {
            int r = (mbase + 16 * mt + g) * LDA + k0 + tig;
            a[mt][0] = __float_as_uint(As[r]);
            a[mt][1] = __float_as_uint(As[r + 8 * LDA]);
            a[mt][2] = __float_as_uint(As[r + 4]);
            a[mt][3] = __float_as_uint(As[r + 8 * LDA + 4]);
        }
#pragma unroll
        for (int nt = 0; nt < 16; nt++) {
            int rb = (nt * 8 + g) * LDB + k0 + tig;
            uint32_t b0 = __float_as_uint(Bs[rb]);
            uint32_t b1 = __float_as_uint(Bs[rb + 4]);
            MMA8(acc[0][nt], a[0], b0, b1);
            MMA8(acc[1][nt], a[1], b0, b1);
        }
    }

    // epilogue 2: scores[l] = b3 + sum_a relu(h2+b2)*w3  (straight from fragments)
    {
        float rs[4] = {0.f, 0.f, 0.f, 0.f};
#pragma unroll
        for (int mt = 0; mt < 2; mt++) {
#pragma unroll
            for (int nt = 0; nt < 16; nt++) {
                int c0 = nt * 8 + 2 * tig;
                float b20 = m->b2v[c0], b21 = m->b2v[c0 + 1];
                float w30 = m->w3v[c0], w31 = m->w3v[c0 + 1];
                rs[mt * 2 + 0] = fmaf(fmaxf(acc[mt][nt][0] + b20, 0.f), w30,
                                 fmaf(fmaxf(acc[mt][nt][1] + b21, 0.f), w31, rs[mt * 2 + 0]));
                rs[mt * 2 + 1] = fmaf(fmaxf(acc[mt][nt][2] + b20, 0.f), w30,
                                 fmaf(fmaxf(acc[mt][nt][3] + b21, 0.f), w31, rs[mt * 2 + 1]));
            }
        }
#pragma unroll
        for (int i = 0; i < 4; i++) {
            rs[i] += __shfl_xor_sync(0xffffffffu, rs[i], 1);
            rs[i] += __shfl_xor_sync(0xffffffffu, rs[i], 2);
        }
        if (tig == 0) {
            float b3v = b3[0];
            m->scores[mbase + g]      = rs[0] + b3v;
            m->scores[mbase + g + 8]  = rs[1] + b3v;
            m->scores[mbase + 16 + g] = rs[2] + b3v;
            m->scores[mbase + 24 + g] = rs[3] + b3v;
        }
    }
    __syncthreads();

    // ---- softmax over valid l (256 threads, one l each) ----
    {
        int l = tid;
        bool valid = l < len;
        float sc = valid ? m->scores[l] : -1e30f;
        float mx = sc;
#pragma unroll
        for (int off = 16; off >= 1; off >>= 1)
            mx = fmaxf(mx, __shfl_xor_sync(0xffffffffu, mx, off));
        if (lane == 0) m->red[wid] = mx;
        __syncthreads();
        if (tid == 0) {
            float M = m->red[0];
            for (int i = 1; i < 8; i++) M = fmaxf(M, m->red[i]);
            m->red[8] = M;
        }
        __syncthreads();
        float M = m->red[8];
        float w = valid ? __expf(sc - M) : 0.f;
        float sum = w;
#pragma unroll
        for (int off = 16; off >= 1; off >>= 1)
            sum += __shfl_xor_sync(0xffffffffu, sum, off);
        if (lane == 0) m->red[wid] = sum;
        __syncthreads();
        if (tid == 0) {
            float S = 0.f;
            for (int i = 0; i < 8; i++) S += m->red[i];
            m->red[9] = S;
        }
        __syncthreads();
        m->wts[l] = w / m->red[9];
    }
    __syncthreads();

    // ---- out[e] = sum_l wts[l] * (keys[b][l][e] + pos[l][e])  (fp32, keys re-read) ----
    {
        int e = tid & 127, half = tid >> 7;
        const float* kb = keys + (size_t)b * L_ * E_ + e;
        const float* pb = pos + e;
        float accO = 0.f;
        int l0 = half * 100, l1 = l0 + 100;
#pragma unroll 4
        for (int l = l0; l < l1; l++)
            accO = fmaf(m->wts[l], __ldg(&kb[(size_t)l * E_]) + pb[(size_t)l * E_], accO);
        m->po[half * 128 + e] = accO;
    }
    __syncthreads();
    if (tid < 128)
        out[(size_t)b * E_ + tid] = m->po[tid] + m->po[128 + tid];
}

// ---------------- entry ----------------
extern "C" void kernel_launch(void* const* d_in, const int* in_sizes, int n_in,
                              void* d_out, int out_size) {
    const float* query = (const float*)d_in[0];
    const float* keys  = (const float*)d_in[1];
    const void*  klen  = d_in[2];
    const float* pos   = (const float*)d_in[3];
    const float* W1    = (const float*)d_in[4];
    const float* b1    = (const float*)d_in[5];
    const float* W2    = (const float*)d_in[6];
    const float* b2    = (const float*)d_in[7];
    const float* W3    = (const float*)d_in[8];
    const float* b3    = (const float*)d_in[9];
    float* out = (float*)d_out;
    (void)in_sizes; (void)n_in; (void)out_size;

    cudaFuncSetAttribute(din_main, cudaFuncAttributeMaxDynamicSharedMemorySize,
                         SMEM_TOTAL);

    prep_wt<<<(A_ * E_ + 255) / 256, 256>>>(W1, W2);
    prep_qw<<<B_, 128>>>(query, W1, b1);
    din_main<<<B_, 256, SMEM_TOTAL>>>(query, keys, klen, pos, b2, W3, b3, out);
}

// round 4
// speedup vs baseline: 8.0956x; 1.7892x over previous
#include <cuda_runtime.h>
#include <cstdint>

#define B_ 4096
#define L_ 200
#define E_ 128
#define A_ 128
#define MR 256              // L padded to 8 warps x 32 rows
#define LDE 136             // bf16 elements per row (17 x 16B -> conflict-free ldmatrix)
#define ROWB 272            // bytes per row
#define ROWU 68             // uint32 per row

// byte offsets inside dynamic smem
#define OFF_KPF 0                       // float kp[200][128]   = 102400 B
#define OFF_AS  102400                  // bf16 As[256][136]    = 69632 B
#define OFF_BS  172032                  // bf16 Bs[128][136]    = 34816 B
#define OFF_MS  206848                  // Misc
// Misc: qv,qwv,b2v,w3v (4*512) + scores,wts (2*1024) + red 64 + po 1024
struct Misc {
    float qv[E_], qwv[A_], b2v[A_], w3v[A_];
    float scores[MR], wts[MR];
    float red[16], po[256];
};
#define SMEM_TOTAL (OFF_MS + (int)sizeof(Misc))

// Global scratch (allocation forbidden)
__device__ float    g_qw[B_ * A_];      // q @ (W1q + W1d) + b1
__device__ float    g_WkT[A_ * E_];     // (W1k - W1d)^T [a][e]
__device__ float    g_WmT[A_ * E_];     // W1m^T         [a][e]
__device__ uint32_t g_W2Tb[A_ * A_ / 2];// W2^T bf16-packed pairs [aout][ain/2]

__device__ __forceinline__ uint32_t smem_u32(const void* p) {
    uint32_t a;
    asm("{ .reg .u64 t; cvta.to.shared.u64 t, %1; cvt.u32.u64 %0, t; }"
        : "=r"(a) : "l"(p));
    return a;
}
__device__ __forceinline__ uint32_t bfpack(float lo, float hi) {
    uint32_t r;
    asm("cvt.rn.bf16x2.f32 %0, %1, %2;" : "=r"(r) : "f"(hi), "f"(lo));
    return r;
}
#define LDSM4(r, addr)                                                         \
    asm volatile("ldmatrix.sync.aligned.m8n8.x4.shared.b16 {%0,%1,%2,%3}, [%4];" \
                 : "=r"((r)[0]), "=r"((r)[1]), "=r"((r)[2]), "=r"((r)[3])      \
                 : "r"(addr))
#define MMAB(d, a, b0, b1)                                                     \
    asm volatile("mma.sync.aligned.m16n8k16.row.col.f32.bf16.bf16.f32 "        \
                 "{%0,%1,%2,%3}, {%4,%5,%6,%7}, {%8,%9}, {%0,%1,%2,%3};"       \
                 : "+f"((d)[0]), "+f"((d)[1]), "+f"((d)[2]), "+f"((d)[3])      \
                 : "r"((a)[0]), "r"((a)[1]), "r"((a)[2]), "r"((a)[3]),         \
                   "r"(b0), "r"(b1))

// ---------------- prep kernels ----------------
__global__ void prep_wt(const float* __restrict__ W1, const float* __restrict__ W2) {
    int idx = blockIdx.x * blockDim.x + threadIdx.x;
    if (idx < A_ * E_) {
        int a = idx >> 7, e = idx & 127;
        g_WkT[a * E_ + e] = W1[(E_ + e) * A_ + a] - W1[(2 * E_ + e) * A_ + a];
        g_WmT[a * E_ + e] = W1[(3 * E_ + e) * A_ + a];
    }
    if (idx < A_ * A_ / 2) {                    // W2^T bf16 pairs along ain
        int a = idx >> 6, p = idx & 63, e = 2 * p;
        float w0 = W2[e * A_ + a], w1 = W2[(e + 1) * A_ + a];
        g_W2Tb[a * 64 + p] = bfpack(w0, w1);
    }
}

__global__ void prep_qw(const float* __restrict__ query,
                        const float* __restrict__ W1,
                        const float* __restrict__ b1) {
    __shared__ float qs[E_];
    int b = blockIdx.x, a = threadIdx.x;
    qs[a] = query[(size_t)b * E_ + a];
    __syncthreads();
    float acc = b1[a];
#pragma unroll 4
    for (int e = 0; e < E_; e++)
        acc = fmaf(qs[e], W1[e * A_ + a] + W1[(2 * E_ + e) * A_ + a], acc);
    g_qw[(size_t)b * A_ + a] = acc;
}

// 128x128-K GEMM for one warp: 32 rows (mbase), all 128 cols, bf16 via ldmatrix
__device__ __forceinline__ void gemm128(uint32_t AsU, uint32_t BsU,
                                        int mbase, int lane,
                                        float acc[2][16][4]) {
    const int r15 = lane & 15;
    const uint32_t aAddr0 = AsU + (uint32_t)((mbase + r15) * ROWB + (lane >> 4) * 16);
    const uint32_t aAddr1 = aAddr0 + 16 * ROWB;
    const int bRow = ((lane >> 4) << 3) + (lane & 7);
    const uint32_t bAddr = BsU + (uint32_t)(bRow * ROWB + ((lane >> 3) & 1) * 16);
#pragma unroll
    for (int k = 0; k < 8; k++) {
        uint32_t a0[4], a1[4];
        LDSM4(a0, aAddr0 + k * 32);
        LDSM4(a1, aAddr1 + k * 32);
#pragma unroll
        for (int np = 0; np < 8; np++) {
            uint32_t bf[4];
            LDSM4(bf, bAddr + np * 16 * ROWB + k * 32);
            MMAB(acc[0][2 * np],     a0, bf[0], bf[1]);
            MMAB(acc[1][2 * np],     a1, bf[0], bf[1]);
            MMAB(acc[0][2 * np + 1], a0, bf[2], bf[3]);
            MMAB(acc[1][2 * np + 1], a1, bf[2], bf[3]);
        }
    }
}

// ---------------- main kernel ----------------
__global__ __launch_bounds__(256, 1) void din_main(
    const float* __restrict__ query,
    const float* __restrict__ keys,
    const void*  __restrict__ len_ptr,
    const float* __restrict__ pos,
    const float* __restrict__ b2,
    const float* __restrict__ W3,
    const float* __restrict__ b3,
    float* __restrict__ out)
{
    extern __shared__ char sm[];
    float*    kpF  = (float*)(sm + OFF_KPF);
    uint32_t* As32 = (uint32_t*)(sm + OFF_AS);
    uint32_t* Bs32 = (uint32_t*)(sm + OFF_BS);
    Misc*     m    = (Misc*)(sm + OFF_MS);
    const uint32_t AsU = smem_u32(sm + OFF_AS);
    const uint32_t BsU = smem_u32(sm + OFF_BS);

    const int b = blockIdx.x;
    const int tid = threadIdx.x;
    const int wid = tid >> 5;
    const int lane = tid & 31;
    const int g = lane >> 2;
    const int tig = lane & 3;
    const int mbase = wid * 32;

    // keys_length dtype sniff (values in [1, L])
    unsigned long long first8 = *(const unsigned long long*)len_ptr;
    int len = (first8 <= (unsigned long long)L_)
            ? (int)((const long long*)len_ptr)[b]
            : ((const int*)len_ptr)[b];

    if (tid < 128) {
        m->qv[tid]  = query[(size_t)b * E_ + tid];
        m->qwv[tid] = g_qw[(size_t)b * A_ + tid];
        m->b2v[tid] = b2[tid];
        m->w3v[tid] = W3[tid];
    }
    __syncthreads();

    // ---- build kpF (fp32) + As (bf16) + Bs = Wc = WkT + q*WmT (bf16) ----
    {
        const float4* k4 = (const float4*)(keys + (size_t)b * L_ * E_);
        const float4* p4 = (const float4*)pos;
        for (int idx = tid; idx < MR * 32; idx += 256) {
            int l = idx >> 5, c4 = idx & 31, e0 = c4 * 4;
            if (l < L_) {
                float4 kv = k4[l * 32 + c4], pv = p4[l * 32 + c4];
                float4 s;
                s.x = kv.x + pv.x; s.y = kv.y + pv.y;
                s.z = kv.z + pv.z; s.w = kv.w + pv.w;
                ((float4*)kpF)[l * 32 + c4] = s;
                As32[l * ROWU + (e0 >> 1)]     = bfpack(s.x, s.y);
                As32[l * ROWU + (e0 >> 1) + 1] = bfpack(s.z, s.w);
            } else {
                As32[l * ROWU + (e0 >> 1)]     = 0u;
                As32[l * ROWU + (e0 >> 1) + 1] = 0u;
            }
        }
        const float4* wk4 = (const float4*)g_WkT;
        const float4* wm4 = (const float4*)g_WmT;
        for (int idx = tid; idx < 128 * 32; idx += 256) {
            int a = idx >> 5, c4 = idx & 31, e0 = c4 * 4;
            float4 wk = wk4[a * 32 + c4], wm = wm4[a * 32 + c4];
            float4 qe = *(const float4*)&m->qv[e0];
            float vx = fmaf(qe.x, wm.x, wk.x), vy = fmaf(qe.y, wm.y, wk.y);
            float vz = fmaf(qe.z, wm.z, wk.z), vw = fmaf(qe.w, wm.w, wk.w);
            Bs32[a * ROWU + (e0 >> 1)]     = bfpack(vx, vy);
            Bs32[a * ROWU + (e0 >> 1) + 1] = bfpack(vz, vw);
        }
    }
    __syncthreads();

    float acc[2][16][4];

    // ================= GEMM1: h1_raw = kp @ Wc^T =================
#pragma unroll
    for (int mt = 0; mt < 2; mt++)
#pragma unroll
        for (int nt = 0; nt < 16; nt++)
#pragma unroll
            for (int j = 0; j < 4; j++) acc[mt][nt][j] = 0.f;

    gemm128(AsU, BsU, mbase, lane, acc);

    // epilogue 1: h1 = relu(acc + qw) -> bf16, overwrite own rows of As
#pragma unroll
    for (int mt = 0; mt < 2; mt++) {
        int r0 = mbase + 16 * mt + g;
#pragma unroll
        for (int nt = 0; nt < 16; nt++) {
            int c0 = nt * 8 + 2 * tig;
            float q0 = m->qwv[c0], q1 = m->qwv[c0 + 1];
            As32[r0 * ROWU + (c0 >> 1)] =
                bfpack(fmaxf(acc[mt][nt][0] + q0, 0.f),
                       fmaxf(acc[mt][nt][1] + q1, 0.f));
            As32[(r0 + 8) * ROWU + (c0 >> 1)] =
                bfpack(fmaxf(acc[mt][nt][2] + q0, 0.f),
                       fmaxf(acc[mt][nt][3] + q1, 0.f));
        }
    }
    __syncthreads();

    // load W2T (pre-packed bf16) into Bs: pure 16B copy
    {
        const uint4* src = (const uint4*)g_W2Tb;
        uint4* dst = (uint4*)Bs32;
        for (int idx = tid; idx < 128 * 16; idx += 256) {
            int row = idx >> 4, c = idx & 15;
            dst[row * 17 + c] = src[row * 16 + c];
        }
    }
    __syncthreads();

    // ================= GEMM2: h2_raw = h1 @ W2 =================
#pragma unroll
    for (int mt = 0; mt < 2; mt++)
#pragma unroll
        for (int nt = 0; nt < 16; nt++)
#pragma unroll
            for (int j = 0; j < 4; j++) acc[mt][nt][j] = 0.f;

    gemm128(AsU, BsU, mbase, lane, acc);

    // epilogue 2: scores[l] = b3 + sum_a relu(h2+b2)*w3  (from fragments)
    {
        float rs[4] = {0.f, 0.f, 0.f, 0.f};
#pragma unroll
        for (int mt = 0; mt < 2; mt++) {
#pragma unroll
            for (int nt = 0; nt < 16; nt++) {
                int c0 = nt * 8 + 2 * tig;
                float b20 = m->b2v[c0], b21 = m->b2v[c0 + 1];
                float w30 = m->w3v[c0], w31 = m->w3v[c0 + 1];
                rs[mt * 2 + 0] = fmaf(fmaxf(acc[mt][nt][0] + b20, 0.f), w30,
                                 fmaf(fmaxf(acc[mt][nt][1] + b21, 0.f), w31, rs[mt * 2 + 0]));
                rs[mt * 2 + 1] = fmaf(fmaxf(acc[mt][nt][2] + b20, 0.f), w30,
                                 fmaf(fmaxf(acc[mt][nt][3] + b21, 0.f), w31, rs[mt * 2 + 1]));
            }
        }
#pragma unroll
        for (int i = 0; i < 4; i++) {
            rs[i] += __shfl_xor_sync(0xffffffffu, rs[i], 1);
            rs[i] += __shfl_xor_sync(0xffffffffu, rs[i], 2);
        }
        if (tig == 0) {
            float b3v = b3[0];
            m->scores[mbase + g]      = rs[0] + b3v;
            m->scores[mbase + g + 8]  = rs[1] + b3v;
            m->scores[mbase + 16 + g] = rs[2] + b3v;
            m->scores[mbase + 24 + g] = rs[3] + b3v;
        }
    }
    __syncthreads();

    // ---- softmax over valid l ----
    {
        int l = tid;
        bool valid = l < len;
        float sc = valid ? m->scores[l] : -1e30f;
        float mx = sc;
#pragma unroll
        for (int off = 16; off >= 1; off >>= 1)
            mx = fmaxf(mx, __shfl_xor_sync(0xffffffffu, mx, off));
        if (lane == 0) m->red[wid] = mx;
        __syncthreads();
        if (tid == 0) {
            float M = m->red[0];
            for (int i = 1; i < 8; i++) M = fmaxf(M, m->red[i]);
            m->red[8] = M;
        }
        __syncthreads();
        float M = m->red[8];
        float w = valid ? __expf(sc - M) : 0.f;
        float sum = w;
#pragma unroll
        for (int off = 16; off >= 1; off >>= 1)
            sum += __shfl_xor_sync(0xffffffffu, sum, off);
        if (lane == 0) m->red[wid] = sum;
        __syncthreads();
        if (tid == 0) {
            float S = 0.f;
            for (int i = 0; i < 8; i++) S += m->red[i];
            m->red[9] = S;
        }
        __syncthreads();
        m->wts[l] = w / m->red[9];
    }
    __syncthreads();

    // ---- out[e] = sum_l wts[l] * kpF[l][e]   (fp32 from smem, no 2nd DRAM read) ----
    {
        int e = tid & 127, half = tid >> 7;
        float accO = 0.f;
        int l0 = half * 100, l1 = l0 + 100;
#pragma unroll 4
        for (int l = l0; l < l1; l++)
            accO = fmaf(m->wts[l], kpF[l * E_ + e], accO);
        m->po[half * 128 + e] = accO;
    }
    __syncthreads();
    if (tid < 128)
        out[(size_t)b * E_ + tid] = m->po[tid] + m->po[128 + tid];
}

// ---------------- entry ----------------
extern "C" void kernel_launch(void* const* d_in, const int* in_sizes, int n_in,
                              void* d_out, int out_size) {
    const float* query = (const float*)d_in[0];
    const float* keys  = (const float*)d_in[1];
    const void*  klen  = d_in[2];
    const float* pos   = (const float*)d_in[3];
    const float* W1    = (const float*)d_in[4];
    const float* b1    = (const float*)d_in[5];
    const float* W2    = (const float*)d_in[6];
    const float* b2    = (const float*)d_in[7];
    const float* W3    = (const float*)d_in[8];
    const float* b3    = (const float*)d_in[9];
    float* out = (float*)d_out;
    (void)in_sizes; (void)n_in; (void)out_size;

    cudaFuncSetAttribute(din_main, cudaFuncAttributeMaxDynamicSharedMemorySize,
                         SMEM_TOTAL);

    prep_wt<<<(A_ * E_ + 255) / 256, 256>>>(W1, W2);
    prep_qw<<<B_, 128>>>(query, W1, b1);
    din_main<<<B_, 256, SMEM_TOTAL>>>(query, keys, klen, pos, b2, W3, b3, out);
}

// round 5
// speedup vs baseline: 10.2598x; 1.2673x over previous
#include <cuda_runtime.h>
#include <cstdint>

#define B_ 4096
#define L_ 200
#define E_ 128
#define A_ 128
#define MR 256              // L padded to 8 warps x 32 rows
#define ROWB 272            // bytes per bf16 row (17 x 16B -> conflict-free ldmatrix)
#define ROWU 68             // uint32 per row

// byte offsets inside dynamic smem (no fp32 kp mirror -> fits 2 CTAs/SM)
#define OFF_AS  0                       // bf16 As[256][136]    = 69632 B
#define OFF_BS  69632                   // bf16 Bs[128][136]    = 34816 B
#define OFF_MS  104448                  // Misc
struct Misc {
    float qv[E_], qwv[A_], b2v[A_], w3v[A_];
    float scores[MR], wts[MR];
    float red[16], po[256];
};
#define SMEM_TOTAL (OFF_MS + (int)sizeof(Misc))   // ~109.6 KB

// Global scratch (allocation forbidden)
__device__ float    g_qw[B_ * A_];      // q @ (W1q + W1d) + b1
__device__ float    g_WkT[A_ * E_];     // (W1k - W1d)^T [a][e]
__device__ float    g_WmT[A_ * E_];     // W1m^T         [a][e]
__device__ uint32_t g_W2Tb[A_ * A_ / 2];// W2^T bf16-packed pairs [aout][ain/2]

__device__ __forceinline__ uint32_t smem_u32(const void* p) {
    uint32_t a;
    asm("{ .reg .u64 t; cvta.to.shared.u64 t, %1; cvt.u32.u64 %0, t; }"
        : "=r"(a) : "l"(p));
    return a;
}
__device__ __forceinline__ uint32_t bfpack(float lo, float hi) {
    uint32_t r;
    asm("cvt.rn.bf16x2.f32 %0, %1, %2;" : "=r"(r) : "f"(hi), "f"(lo));
    return r;
}
#define LDSM4(r, addr)                                                         \
    asm volatile("ldmatrix.sync.aligned.m8n8.x4.shared.b16 {%0,%1,%2,%3}, [%4];" \
                 : "=r"((r)[0]), "=r"((r)[1]), "=r"((r)[2]), "=r"((r)[3])      \
                 : "r"(addr))
#define MMAB(d, a, b0, b1)                                                     \
    asm volatile("mma.sync.aligned.m16n8k16.row.col.f32.bf16.bf16.f32 "        \
                 "{%0,%1,%2,%3}, {%4,%5,%6,%7}, {%8,%9}, {%0,%1,%2,%3};"       \
                 : "+f"((d)[0]), "+f"((d)[1]), "+f"((d)[2]), "+f"((d)[3])      \
                 : "r"((a)[0]), "r"((a)[1]), "r"((a)[2]), "r"((a)[3]),         \
                   "r"(b0), "r"(b1))

// ---------------- prep kernels ----------------
__global__ void prep_wt(const float* __restrict__ W1, const float* __restrict__ W2) {
    int idx = blockIdx.x * blockDim.x + threadIdx.x;
    if (idx < A_ * E_) {
        int a = idx >> 7, e = idx & 127;
        g_WkT[a * E_ + e] = W1[(E_ + e) * A_ + a] - W1[(2 * E_ + e) * A_ + a];
        g_WmT[a * E_ + e] = W1[(3 * E_ + e) * A_ + a];
    }
    if (idx < A_ * A_ / 2) {                    // W2^T bf16 pairs along ain
        int a = idx >> 6, p = idx & 63, e = 2 * p;
        g_W2Tb[a * 64 + p] = bfpack(W2[e * A_ + a], W2[(e + 1) * A_ + a]);
    }
}

__global__ void prep_qw(const float* __restrict__ query,
                        const float* __restrict__ W1,
                        const float* __restrict__ b1) {
    __shared__ float qs[E_];
    int b = blockIdx.x, a = threadIdx.x;
    qs[a] = query[(size_t)b * E_ + a];
    __syncthreads();
    float acc = b1[a];
#pragma unroll 4
    for (int e = 0; e < E_; e++)
        acc = fmaf(qs[e], W1[e * A_ + a] + W1[(2 * E_ + e) * A_ + a], acc);
    g_qw[(size_t)b * A_ + a] = acc;
}

// One 16-row x 128-col x 128-K bf16 GEMM half for one warp.
// rowbase = absolute first row of this 16-row slab. acc[16][4].
__device__ __forceinline__ void gemm16(uint32_t AsU, uint32_t BsU,
                                       int rowbase, int lane,
                                       float acc[16][4]) {
    const uint32_t aAddr = AsU +
        (uint32_t)((rowbase + (lane & 15)) * ROWB + (lane >> 4) * 16);
    const int bRow = ((lane >> 4) << 3) + (lane & 7);
    const uint32_t bAddr = BsU + (uint32_t)(bRow * ROWB + ((lane >> 3) & 1) * 16);
#pragma unroll
    for (int k = 0; k < 8; k++) {
        uint32_t a[4];
        LDSM4(a, aAddr + k * 32);
#pragma unroll
        for (int np = 0; np < 8; np++) {
            uint32_t bf[4];
            LDSM4(bf, bAddr + np * 16 * ROWB + k * 32);
            MMAB(acc[2 * np],     a, bf[0], bf[1]);
            MMAB(acc[2 * np + 1], a, bf[2], bf[3]);
        }
    }
}

// ---------------- main kernel ----------------
__global__ __launch_bounds__(256, 2) void din_main(
    const float* __restrict__ query,
    const float* __restrict__ keys,
    const void*  __restrict__ len_ptr,
    const float* __restrict__ pos,
    const float* __restrict__ b2,
    const float* __restrict__ W3,
    const float* __restrict__ b3,
    float* __restrict__ out)
{
    extern __shared__ char sm[];
    uint32_t* As32 = (uint32_t*)(sm + OFF_AS);
    uint32_t* Bs32 = (uint32_t*)(sm + OFF_BS);
    Misc*     m    = (Misc*)(sm + OFF_MS);
    const uint32_t AsU = smem_u32(sm + OFF_AS);
    const uint32_t BsU = smem_u32(sm + OFF_BS);

    const int b = blockIdx.x;
    const int tid = threadIdx.x;
    const int wid = tid >> 5;
    const int lane = tid & 31;
    const int g = lane >> 2;
    const int tig = lane & 3;
    const int mbase = wid * 32;

    // keys_length dtype sniff (values in [1, L])
    unsigned long long first8 = *(const unsigned long long*)len_ptr;
    int len = (first8 <= (unsigned long long)L_)
            ? (int)((const long long*)len_ptr)[b]
            : ((const int*)len_ptr)[b];

    if (tid < 128) {
        m->qv[tid]  = query[(size_t)b * E_ + tid];
        m->qwv[tid] = g_qw[(size_t)b * A_ + tid];
        m->b2v[tid] = b2[tid];
        m->w3v[tid] = W3[tid];
    }
    __syncthreads();

    // ---- build As = bf16(keys+pos) (zero pad rows >= L), Bs = bf16(Wc) ----
    {
        const float4* k4 = (const float4*)(keys + (size_t)b * L_ * E_);
        const float4* p4 = (const float4*)pos;
        for (int idx = tid; idx < MR * 32; idx += 256) {
            int l = idx >> 5, c4 = idx & 31, e0 = c4 * 4;
            if (l < L_) {
                float4 kv = k4[l * 32 + c4], pv = p4[l * 32 + c4];
                As32[l * ROWU + (e0 >> 1)]     = bfpack(kv.x + pv.x, kv.y + pv.y);
                As32[l * ROWU + (e0 >> 1) + 1] = bfpack(kv.z + pv.z, kv.w + pv.w);
            } else {
                As32[l * ROWU + (e0 >> 1)]     = 0u;
                As32[l * ROWU + (e0 >> 1) + 1] = 0u;
            }
        }
        const float4* wk4 = (const float4*)g_WkT;
        const float4* wm4 = (const float4*)g_WmT;
        for (int idx = tid; idx < 128 * 32; idx += 256) {
            int a = idx >> 5, c4 = idx & 31, e0 = c4 * 4;
            float4 wk = wk4[a * 32 + c4], wm = wm4[a * 32 + c4];
            float4 qe = *(const float4*)&m->qv[e0];
            Bs32[a * ROWU + (e0 >> 1)] =
                bfpack(fmaf(qe.x, wm.x, wk.x), fmaf(qe.y, wm.y, wk.y));
            Bs32[a * ROWU + (e0 >> 1) + 1] =
                bfpack(fmaf(qe.z, wm.z, wk.z), fmaf(qe.w, wm.w, wk.w));
        }
    }
    __syncthreads();

    // ================= GEMM1: h1 = relu(kp @ Wc^T + qw), two 16-row halves ===
    // Each half reads only this warp's own A rows, then overwrites exactly
    // those rows with bf16 h1 -> no barrier needed inside.
#pragma unroll 1
    for (int mh = 0; mh < 2; mh++) {
        float acc[16][4];
#pragma unroll
        for (int nt = 0; nt < 16; nt++)
#pragma unroll
            for (int j = 0; j < 4; j++) acc[nt][j] = 0.f;

        int rowbase = mbase + 16 * mh;
        gemm16(AsU, BsU, rowbase, lane, acc);

        int r0 = rowbase + g;
#pragma unroll
        for (int nt = 0; nt < 16; nt++) {
            int c0 = nt * 8 + 2 * tig;
            float q0 = m->qwv[c0], q1 = m->qwv[c0 + 1];
            As32[r0 * ROWU + (c0 >> 1)] =
                bfpack(fmaxf(acc[nt][0] + q0, 0.f), fmaxf(acc[nt][1] + q1, 0.f));
            As32[(r0 + 8) * ROWU + (c0 >> 1)] =
                bfpack(fmaxf(acc[nt][2] + q0, 0.f), fmaxf(acc[nt][3] + q1, 0.f));
        }
    }
    __syncthreads();

    // load W2T (pre-packed bf16) into Bs: pure 16B copy
    {
        const uint4* src = (const uint4*)g_W2Tb;
        uint4* dst = (uint4*)Bs32;
        for (int idx = tid; idx < 128 * 16; idx += 256) {
            int row = idx >> 4, c = idx & 15;
            dst[row * 17 + c] = src[row * 16 + c];
        }
    }
    __syncthreads();

    // ================= GEMM2 + score epilogue, two 16-row halves =============
    {
        float b3v = b3[0];
#pragma unroll 1
        for (int mh = 0; mh < 2; mh++) {
            float acc[16][4];
#pragma unroll
            for (int nt = 0; nt < 16; nt++)
#pragma unroll
                for (int j = 0; j < 4; j++) acc[nt][j] = 0.f;

            int rowbase = mbase + 16 * mh;
            gemm16(AsU, BsU, rowbase, lane, acc);

            float rs0 = 0.f, rs1 = 0.f;
#pragma unroll
            for (int nt = 0; nt < 16; nt++) {
                int c0 = nt * 8 + 2 * tig;
                float b20 = m->b2v[c0], b21 = m->b2v[c0 + 1];
                float w30 = m->w3v[c0], w31 = m->w3v[c0 + 1];
                rs0 = fmaf(fmaxf(acc[nt][0] + b20, 0.f), w30,
                      fmaf(fmaxf(acc[nt][1] + b21, 0.f), w31, rs0));
                rs1 = fmaf(fmaxf(acc[nt][2] + b20, 0.f), w30,
                      fmaf(fmaxf(acc[nt][3] + b21, 0.f), w31, rs1));
            }
            rs0 += __shfl_xor_sync(0xffffffffu, rs0, 1);
            rs0 += __shfl_xor_sync(0xffffffffu, rs0, 2);
            rs1 += __shfl_xor_sync(0xffffffffu, rs1, 1);
            rs1 += __shfl_xor_sync(0xffffffffu, rs1, 2);
            if (tig == 0) {
                m->scores[rowbase + g]     = rs0 + b3v;
                m->scores[rowbase + 8 + g] = rs1 + b3v;
            }
        }
    }
    __syncthreads();

    // ---- softmax over valid l ----
    {
        int l = tid;
        bool valid = l < len;
        float sc = valid ? m->scores[l] : -1e30f;
        float mx = sc;
#pragma unroll
        for (int off = 16; off >= 1; off >>= 1)
            mx = fmaxf(mx, __shfl_xor_sync(0xffffffffu, mx, off));
        if (lane == 0) m->red[wid] = mx;
        __syncthreads();
        if (tid == 0) {
            float M = m->red[0];
            for (int i = 1; i < 8; i++) M = fmaxf(M, m->red[i]);
            m->red[8] = M;
        }
        __syncthreads();
        float M = m->red[8];
        float w = valid ? __expf(sc - M) : 0.f;
        float sum = w;
#pragma unroll
        for (int off = 16; off >= 1; off >>= 1)
            sum += __shfl_xor_sync(0xffffffffu, sum, off);
        if (lane == 0) m->red[wid] = sum;
        __syncthreads();
        if (tid == 0) {
            float S = 0.f;
            for (int i = 0; i < 8; i++) S += m->red[i];
            m->red[9] = S;
        }
        __syncthreads();
        m->wts[l] = w / m->red[9];
    }
    __syncthreads();

    // ---- out[e] = sum_l wts[l] * (keys[b][l][e] + pos[l][e])  (fp32 re-read) ----
    {
        int e = tid & 127, half = tid >> 7;
        const float* kb = keys + (size_t)b * L_ * E_ + e;
        const float* pb = pos + e;
        float accO = 0.f;
        int l0 = half * 100, l1 = l0 + 100;
#pragma unroll 4
        for (int l = l0; l < l1; l++)
            accO = fmaf(m->wts[l], __ldg(&kb[(size_t)l * E_]) + pb[(size_t)l * E_], accO);
        m->po[half * 128 + e] = accO;
    }
    __syncthreads();
    if (tid < 128)
        out[(size_t)b * E_ + tid] = m->po[tid] + m->po[128 + tid];
}

// ---------------- entry ----------------
extern "C" void kernel_launch(void* const* d_in, const int* in_sizes, int n_in,
                              void* d_out, int out_size) {
    const float* query = (const float*)d_in[0];
    const float* keys  = (const float*)d_in[1];
    const void*  klen  = d_in[2];
    const float* pos   = (const float*)d_in[3];
    const float* W1    = (const float*)d_in[4];
    const float* b1    = (const float*)d_in[5];
    const float* W2    = (const float*)d_in[6];
    const float* b2    = (const float*)d_in[7];
    const float* W3    = (const float*)d_in[8];
    const float* b3    = (const float*)d_in[9];
    float* out = (float*)d_out;
    (void)in_sizes; (void)n_in; (void)out_size;

    cudaFuncSetAttribute(din_main, cudaFuncAttributeMaxDynamicSharedMemorySize,
                         SMEM_TOTAL);

    prep_wt<<<(A_ * E_ + 255) / 256, 256>>>(W1, W2);
    prep_qw<<<B_, 128>>>(query, W1, b1);
    din_main<<<B_, 256, SMEM_TOTAL>>>(query, keys, klen, pos, b2, W3, b3, out);
}

// round 6
// speedup vs baseline: 11.8769x; 1.1576x over previous
#include <cuda_runtime.h>
#include <cstdint>

#define B_ 4096
#define L_ 200
#define E_ 128
#define A_ 128
#define MRp 208             // 13 slabs x 16 rows (L=200 padded minimally)
#define ROWB 272            // bytes per bf16 row (17 x 16B -> conflict-free ldmatrix)
#define ROWU 68             // uint32 per row

// dynamic smem layout
#define OFF_AS 0                         // bf16 As[208][136] = 56576 B (kp only)
#define OFF_BS 56576                     // bf16 Bs[128][136] = 34816 B (Wc, then W2T)
#define OFF_MS 91392
struct Misc {
    float qv[E_], qwv[A_], b2v[A_], w3v[A_];
    float scores[256], wts[256];
    float red[16], po[256];
};
#define SMEM_TOTAL (OFF_MS + (int)sizeof(Misc))   // ~96.6 KB -> 2 CTAs/SM

// Global scratch (allocation forbidden)
__device__ float    g_qw[B_ * A_];       // q @ (W1q + W1d) + b1
__device__ float    g_W1c[E_ * A_];      // W1q + W1d   [e][a]
__device__ float    g_WkT[A_ * E_];      // (W1k - W1d)^T [a][e]
__device__ float    g_WmT[A_ * E_];      // W1m^T         [a][e]
__device__ uint32_t g_W2Tb[A_ * A_ / 2]; // W2^T bf16 pairs [aout][ain/2]

__device__ __forceinline__ uint32_t smem_u32(const void* p) {
    uint32_t a;
    asm("{ .reg .u64 t; cvta.to.shared.u64 t, %1; cvt.u32.u64 %0, t; }"
        : "=r"(a) : "l"(p));
    return a;
}
__device__ __forceinline__ uint32_t bfpack(float lo, float hi) {
    uint32_t r;
    asm("cvt.rn.bf16x2.f32 %0, %1, %2;" : "=r"(r) : "f"(hi), "f"(lo));
    return r;
}
#define LDSM4(r, addr)                                                         \
    asm volatile("ldmatrix.sync.aligned.m8n8.x4.shared.b16 {%0,%1,%2,%3}, [%4];" \
                 : "=r"((r)[0]), "=r"((r)[1]), "=r"((r)[2]), "=r"((r)[3])      \
                 : "r"(addr))
#define MMAB(d, a, b0, b1)                                                     \
    asm volatile("mma.sync.aligned.m16n8k16.row.col.f32.bf16.bf16.f32 "        \
                 "{%0,%1,%2,%3}, {%4,%5,%6,%7}, {%8,%9}, {%0,%1,%2,%3};"       \
                 : "+f"((d)[0]), "+f"((d)[1]), "+f"((d)[2]), "+f"((d)[3])      \
                 : "r"((a)[0]), "r"((a)[1]), "r"((a)[2]), "r"((a)[3]),         \
                   "r"(b0), "r"(b1))

// ---------------- prep kernels ----------------
__global__ void prep_wt(const float* __restrict__ W1, const float* __restrict__ W2) {
    int idx = blockIdx.x * blockDim.x + threadIdx.x;
    if (idx < A_ * E_) {
        int a = idx >> 7, e = idx & 127;
        g_WkT[a * E_ + e] = W1[(E_ + e) * A_ + a] - W1[(2 * E_ + e) * A_ + a];
        g_WmT[a * E_ + e] = W1[(3 * E_ + e) * A_ + a];
        g_W1c[idx] = W1[idx] + W1[2 * E_ * A_ + idx];       // [e][a] row-major
    }
    if (idx < A_ * A_ / 2) {
        int a = idx >> 6, p = idx & 63, e = 2 * p;
        g_W2Tb[a * 64 + p] = bfpack(W2[e * A_ + a], W2[(e + 1) * A_ + a]);
    }
}

// qw for 32 batch rows per block; W1c staged once in smem (64 KB dynamic)
__global__ __launch_bounds__(256) void prep_qw2(const float* __restrict__ query,
                                                const float* __restrict__ b1) {
    extern __shared__ float w[];               // [E_][A_]
    __shared__ float qsh[32 * E_];
    int b0 = blockIdx.x * 32;
    for (int i = threadIdx.x; i < E_ * A_ / 4; i += 256)
        ((float4*)w)[i] = ((const float4*)g_W1c)[i];
    for (int i = threadIdx.x; i < 32 * E_ / 4; i += 256)
        ((float4*)qsh)[i] = ((const float4*)(query + (size_t)b0 * E_))[i];
    __syncthreads();
    int r = threadIdx.x >> 3;                  // 0..31
    int a0 = (threadIdx.x & 7) * 4;            // interleaved cols: a0 + 32j + i
    float acc[4][4];
#pragma unroll
    for (int j = 0; j < 4; j++)
#pragma unroll
        for (int i = 0; i < 4; i++) acc[j][i] = b1[a0 + 32 * j + i];
#pragma unroll 4
    for (int e = 0; e < E_; e++) {
        float qv = qsh[r * E_ + e];
#pragma unroll
        for (int j = 0; j < 4; j++) {
            float4 wv = *(const float4*)&w[e * A_ + a0 + 32 * j];
            acc[j][0] = fmaf(qv, wv.x, acc[j][0]);
            acc[j][1] = fmaf(qv, wv.y, acc[j][1]);
            acc[j][2] = fmaf(qv, wv.z, acc[j][2]);
            acc[j][3] = fmaf(qv, wv.w, acc[j][3]);
        }
    }
#pragma unroll
    for (int j = 0; j < 4; j++)
        *(float4*)&g_qw[(size_t)(b0 + r) * A_ + a0 + 32 * j] =
            make_float4(acc[j][0], acc[j][1], acc[j][2], acc[j][3]);
}

// ---------------- warp GEMM bodies ----------------
// GEMM1: NM m16-slabs x 128 cols x 128 K; output packed straight into
// GEMM2 A-fragments (h1f). N processed in 32-col quarters (acc = NM*16 regs).
template <int NM>
__device__ __forceinline__ void gemm1_reg(uint32_t AsU, uint32_t BsU,
                                          const float* __restrict__ qwv,
                                          int rowbase, int lane,
                                          uint32_t h1f[][8][4]) {
    const int tig = lane & 3;
    const uint32_t aAddr = AsU +
        (uint32_t)((rowbase + (lane & 15)) * ROWB + (lane >> 4) * 16);
    const int bRow = ((lane >> 4) << 3) + (lane & 7);
    const uint32_t bAddr = BsU + (uint32_t)(bRow * ROWB + ((lane >> 3) & 1) * 16);
#pragma unroll
    for (int qh = 0; qh < 4; qh++) {
        float acc[NM][4][4];
#pragma unroll
        for (int mt = 0; mt < NM; mt++)
#pragma unroll
            for (int nt = 0; nt < 4; nt++)
#pragma unroll
                for (int j = 0; j < 4; j++) acc[mt][nt][j] = 0.f;
#pragma unroll
        for (int kc = 0; kc < 8; kc++) {
            uint32_t a[NM][4];
#pragma unroll
            for (int mt = 0; mt < NM; mt++)
                LDSM4(a[mt], aAddr + mt * 16 * ROWB + kc * 32);
#pragma unroll
            for (int npl = 0; npl < 2; npl++) {
                uint32_t bf[4];
                LDSM4(bf, bAddr + (qh * 32 + npl * 16) * ROWB + kc * 32);
#pragma unroll
                for (int mt = 0; mt < NM; mt++) {
                    MMAB(acc[mt][2 * npl],     a[mt], bf[0], bf[1]);
                    MMAB(acc[mt][2 * npl + 1], a[mt], bf[2], bf[3]);
                }
            }
        }
        // relu(+qw) and pack: acc tile ntg -> A-frag slot of k-chunk ntg>>1
#pragma unroll
        for (int mt = 0; mt < NM; mt++)
#pragma unroll
            for (int ntl = 0; ntl < 4; ntl++) {
                int ntg = qh * 4 + ntl;
                int c0 = ntg * 8 + 2 * tig;
                float q0 = qwv[c0], q1 = qwv[c0 + 1];
                int kcg = ntg >> 1, hf = (ntg & 1) << 1;
                h1f[mt][kcg][hf] =
                    bfpack(fmaxf(acc[mt][ntl][0] + q0, 0.f),
                           fmaxf(acc[mt][ntl][1] + q1, 0.f));
                h1f[mt][kcg][hf + 1] =
                    bfpack(fmaxf(acc[mt][ntl][2] + q0, 0.f),
                           fmaxf(acc[mt][ntl][3] + q1, 0.f));
            }
    }
}

// GEMM2: A = h1f (registers), B = W2T in smem; fused score dot per quarter.
template <int NM>
__device__ __forceinline__ void gemm2_reg(uint32_t BsU, const float* __restrict__ b2v,
                                          const float* __restrict__ w3v, int lane,
                                          uint32_t h1f[][8][4], float rs[4]) {
    const int tig = lane & 3;
    const int bRow = ((lane >> 4) << 3) + (lane & 7);
    const uint32_t bAddr = BsU + (uint32_t)(bRow * ROWB + ((lane >> 3) & 1) * 16);
#pragma unroll
    for (int qh = 0; qh < 4; qh++) {
        float acc[NM][4][4];
#pragma unroll
        for (int mt = 0; mt < NM; mt++)
#pragma unroll
            for (int nt = 0; nt < 4; nt++)
#pragma unroll
                for (int j = 0; j < 4; j++) acc[mt][nt][j] = 0.f;
#pragma unroll
        for (int kc = 0; kc < 8; kc++) {
#pragma unroll
            for (int npl = 0; npl < 2; npl++) {
                uint32_t bf[4];
                LDSM4(bf, bAddr + (qh * 32 + npl * 16) * ROWB + kc * 32);
#pragma unroll
                for (int mt = 0; mt < NM; mt++) {
                    MMAB(acc[mt][2 * npl],     h1f[mt][kc], bf[0], bf[1]);
                    MMAB(acc[mt][2 * npl + 1], h1f[mt][kc], bf[2], bf[3]);
                }
            }
        }
#pragma unroll
        for (int mt = 0; mt < NM; mt++)
#pragma unroll
            for (int ntl = 0; ntl < 4; ntl++) {
                int c0 = qh * 32 + ntl * 8 + 2 * tig;
                float b20 = b2v[c0], b21 = b2v[c0 + 1];
                float w30 = w3v[c0], w31 = w3v[c0 + 1];
                rs[2 * mt + 0] = fmaf(fmaxf(acc[mt][ntl][0] + b20, 0.f), w30,
                                 fmaf(fmaxf(acc[mt][ntl][1] + b21, 0.f), w31, rs[2 * mt + 0]));
                rs[2 * mt + 1] = fmaf(fmaxf(acc[mt][ntl][2] + b20, 0.f), w30,
                                 fmaf(fmaxf(acc[mt][ntl][3] + b21, 0.f), w31, rs[2 * mt + 1]));
            }
    }
}

// ---------------- main kernel ----------------
__global__ __launch_bounds__(256, 2) void din_main(
    const float* __restrict__ query,
    const float* __restrict__ keys,
    const void*  __restrict__ len_ptr,
    const float* __restrict__ pos,
    const float* __restrict__ b2,
    const float* __restrict__ W3,
    const float* __restrict__ b3,
    float* __restrict__ out)
{
    extern __shared__ char sm[];
    uint32_t* As32 = (uint32_t*)(sm + OFF_AS);
    uint32_t* Bs32 = (uint32_t*)(sm + OFF_BS);
    Misc*     m    = (Misc*)(sm + OFF_MS);
    const uint32_t AsU = smem_u32(sm + OFF_AS);
    const uint32_t BsU = smem_u32(sm + OFF_BS);

    const int b = blockIdx.x;
    const int tid = threadIdx.x;
    const int wid = tid >> 5;
    const int lane = tid & 31;
    const int g = lane >> 2;
    const int tig = lane & 3;

    // keys_length dtype sniff (values in [1, L])
    unsigned long long first8 = *(const unsigned long long*)len_ptr;
    int len = (first8 <= (unsigned long long)L_)
            ? (int)((const long long*)len_ptr)[b]
            : ((const int*)len_ptr)[b];

    if (tid < 128) {
        m->qv[tid]  = query[(size_t)b * E_ + tid];
        m->qwv[tid] = g_qw[(size_t)b * A_ + tid];
        m->b2v[tid] = b2[tid];
        m->w3v[tid] = W3[tid];
    }
    __syncthreads();

    // ---- build As = bf16(keys+pos) (208 rows, zero-pad >= L), Bs = bf16(Wc) ----
    {
        const float4* k4 = (const float4*)(keys + (size_t)b * L_ * E_);
        const float4* p4 = (const float4*)pos;
        for (int idx = tid; idx < MRp * 32; idx += 256) {
            int l = idx >> 5, c4 = idx & 31, e0 = c4 * 4;
            if (l < L_) {
                float4 kv = k4[l * 32 + c4], pv = p4[l * 32 + c4];
                As32[l * ROWU + (e0 >> 1)]     = bfpack(kv.x + pv.x, kv.y + pv.y);
                As32[l * ROWU + (e0 >> 1) + 1] = bfpack(kv.z + pv.z, kv.w + pv.w);
            } else {
                As32[l * ROWU + (e0 >> 1)]     = 0u;
                As32[l * ROWU + (e0 >> 1) + 1] = 0u;
            }
        }
        const float4* wk4 = (const float4*)g_WkT;
        const float4* wm4 = (const float4*)g_WmT;
        for (int idx = tid; idx < 128 * 32; idx += 256) {
            int a = idx >> 5, c4 = idx & 31, e0 = c4 * 4;
            float4 wk = wk4[a * 32 + c4], wm = wm4[a * 32 + c4];
            float4 qe = *(const float4*)&m->qv[e0];
            Bs32[a * ROWU + (e0 >> 1)] =
                bfpack(fmaf(qe.x, wm.x, wk.x), fmaf(qe.y, wm.y, wk.y));
            Bs32[a * ROWU + (e0 >> 1) + 1] =
                bfpack(fmaf(qe.z, wm.z, wk.z), fmaf(qe.w, wm.w, wk.w));
        }
    }
    __syncthreads();

    // ---- GEMM1 (h1 stays in registers as GEMM2 A-fragments) ----
    uint32_t h1f[2][8][4];
    if (wid < 6)       gemm1_reg<2>(AsU, BsU, m->qwv, wid * 32, lane, h1f);
    else if (wid == 6) gemm1_reg<1>(AsU, BsU, m->qwv, 192, lane, h1f);
    __syncthreads();                     // all warps done reading Bs (Wc)

    // overwrite Bs with pre-packed bf16 W2T
    {
        const uint4* src = (const uint4*)g_W2Tb;
        uint4* dst = (uint4*)Bs32;
        for (int idx = tid; idx < 128 * 16; idx += 256) {
            int row = idx >> 4, c = idx & 15;
            dst[row * 17 + c] = src[row * 16 + c];
        }
    }
    __syncthreads();

    // ---- GEMM2 + score epilogue ----
    float rs[4] = {0.f, 0.f, 0.f, 0.f};
    if (wid < 6)       gemm2_reg<2>(BsU, m->b2v, m->w3v, lane, h1f, rs);
    else if (wid == 6) gemm2_reg<1>(BsU, m->b2v, m->w3v, lane, h1f, rs);
#pragma unroll
    for (int i = 0; i < 4; i++) {
        rs[i] += __shfl_xor_sync(0xffffffffu, rs[i], 1);
        rs[i] += __shfl_xor_sync(0xffffffffu, rs[i], 2);
    }
    if (tig == 0 && wid < 7) {
        float b3v = b3[0];
        int rowbase = wid * 32;
        m->scores[rowbase + g]     = rs[0] + b3v;
        m->scores[rowbase + 8 + g] = rs[1] + b3v;
        if (wid < 6) {
            m->scores[rowbase + 16 + g] = rs[2] + b3v;
            m->scores[rowbase + 24 + g] = rs[3] + b3v;
        }
    }
    __syncthreads();

    // ---- softmax over valid l ----
    {
        int l = tid;
        bool valid = l < len;
        float sc = valid ? m->scores[l] : -1e30f;
        float mx = sc;
#pragma unroll
        for (int off = 16; off >= 1; off >>= 1)
            mx = fmaxf(mx, __shfl_xor_sync(0xffffffffu, mx, off));
        if (lane == 0) m->red[wid] = mx;
        __syncthreads();
        if (tid == 0) {
            float M = m->red[0];
            for (int i = 1; i < 8; i++) M = fmaxf(M, m->red[i]);
            m->red[8] = M;
        }
        __syncthreads();
        float M = m->red[8];
        float w = valid ? __expf(sc - M) : 0.f;
        float sum = w;
#pragma unroll
        for (int off = 16; off >= 1; off >>= 1)
            sum += __shfl_xor_sync(0xffffffffu, sum, off);
        if (lane == 0) m->red[wid] = sum;
        __syncthreads();
        if (tid == 0) {
            float S = 0.f;
            for (int i = 0; i < 8; i++) S += m->red[i];
            m->red[9] = S;
        }
        __syncthreads();
        m->wts[l] = w / m->red[9];
    }
    __syncthreads();

    // ---- out[e] = sum_l wts[l] * (keys[b][l][e] + pos[l][e])  (fp32 re-read) ----
    {
        int e = tid & 127, half = tid >> 7;
        const float* kb = keys + (size_t)b * L_ * E_ + e;
        const float* pb = pos + e;
        float accO = 0.f;
        int l0 = half * 100, l1 = l0 + 100;
#pragma unroll 4
        for (int l = l0; l < l1; l++)
            accO = fmaf(m->wts[l], __ldg(&kb[(size_t)l * E_]) + pb[(size_t)l * E_], accO);
        m->po[half * 128 + e] = accO;
    }
    __syncthreads();
    if (tid < 128)
        out[(size_t)b * E_ + tid] = m->po[tid] + m->po[128 + tid];
}

// ---------------- entry ----------------
extern "C" void kernel_launch(void* const* d_in, const int* in_sizes, int n_in,
                              void* d_out, int out_size) {
    const float* query = (const float*)d_in[0];
    const float* keys  = (const float*)d_in[1];
    const void*  klen  = d_in[2];
    const float* pos   = (const float*)d_in[3];
    const float* W1    = (const float*)d_in[4];
    const float* b1    = (const float*)d_in[5];
    const float* W2    = (const float*)d_in[6];
    const float* b2    = (const float*)d_in[7];
    const float* W3    = (const float*)d_in[8];
    const float* b3    = (const float*)d_in[9];
    float* out = (float*)d_out;
    (void)in_sizes; (void)n_in; (void)out_size;

    cudaFuncSetAttribute(din_main, cudaFuncAttributeMaxDynamicSharedMemorySize,
                         SMEM_TOTAL);
    cudaFuncSetAttribute(prep_qw2, cudaFuncAttributeMaxDynamicSharedMemorySize,
                         E_ * A_ * 4);

    prep_wt<<<(A_ * E_ + 255) / 256, 256>>>(W1, W2);
    prep_qw2<<<B_ / 32, 256, E_ * A_ * 4>>>(query, b1);
    din_main<<<B_, 256, SMEM_TOTAL>>>(query, keys, klen, pos, b2, W3, b3, out);
}

// round 7
// speedup vs baseline: 17.1815x; 1.4466x over previous
#include <cuda_runtime.h>
#include <cstdint>

#define B_ 4096
#define L_ 200
#define E_ 128
#define A_ 128
#define MRp 208             // max 13 slabs x 16 rows
#define ROWB 272            // bytes per bf16 row (17 x 16B -> conflict-free ldmatrix)
#define ROWU 68             // uint32 per row

// dynamic smem layout
#define OFF_AS 0                         // bf16 As[208][136] = 56576 B (kp only)
#define OFF_BS 56576                     // bf16 Bs[128][136] = 34816 B (Wc, then W2T)
#define OFF_MS 91392
struct Misc {
    float qv[E_], qwv[A_], b2v[A_], w3v[A_];
    float scores[256], wts[256];
    float red[16], po[256];
};
#define SMEM_TOTAL (OFF_MS + (int)sizeof(Misc))   // ~96.6 KB -> 2 CTAs/SM

// Global scratch (allocation forbidden)
__device__ float    g_qw[B_ * A_];       // q @ (W1q + W1d) + b1
__device__ float    g_W1c[E_ * A_];      // W1q + W1d   [e][a]
__device__ float    g_WkT[A_ * E_];      // (W1k - W1d)^T [a][e]
__device__ float    g_WmT[A_ * E_];      // W1m^T         [a][e]
__device__ uint32_t g_W2Tb[A_ * A_ / 2]; // W2^T bf16 pairs [aout][ain/2]

__device__ __forceinline__ uint32_t smem_u32(const void* p) {
    uint32_t a;
    asm("{ .reg .u64 t; cvta.to.shared.u64 t, %1; cvt.u32.u64 %0, t; }"
        : "=r"(a) : "l"(p));
    return a;
}
__device__ __forceinline__ uint32_t bfpack(float lo, float hi) {
    uint32_t r;
    asm("cvt.rn.bf16x2.f32 %0, %1, %2;" : "=r"(r) : "f"(hi), "f"(lo));
    return r;
}
#define LDSM4(r, addr)                                                         \
    asm volatile("ldmatrix.sync.aligned.m8n8.x4.shared.b16 {%0,%1,%2,%3}, [%4];" \
                 : "=r"((r)[0]), "=r"((r)[1]), "=r"((r)[2]), "=r"((r)[3])      \
                 : "r"(addr))
#define MMAB(d, a, b0, b1)                                                     \
    asm volatile("mma.sync.aligned.m16n8k16.row.col.f32.bf16.bf16.f32 "        \
                 "{%0,%1,%2,%3}, {%4,%5,%6,%7}, {%8,%9}, {%0,%1,%2,%3};"       \
                 : "+f"((d)[0]), "+f"((d)[1]), "+f"((d)[2]), "+f"((d)[3])      \
                 : "r"((a)[0]), "r"((a)[1]), "r"((a)[2]), "r"((a)[3]),         \
                   "r"(b0), "r"(b1))

// ---------------- prep kernels ----------------
__global__ void prep_wt(const float* __restrict__ W1, const float* __restrict__ W2) {
    int idx = blockIdx.x * blockDim.x + threadIdx.x;
    if (idx < A_ * E_) {
        int a = idx >> 7, e = idx & 127;
        g_WkT[a * E_ + e] = W1[(E_ + e) * A_ + a] - W1[(2 * E_ + e) * A_ + a];
        g_WmT[a * E_ + e] = W1[(3 * E_ + e) * A_ + a];
        g_W1c[idx] = W1[idx] + W1[2 * E_ * A_ + idx];
    }
    if (idx < A_ * A_ / 2) {
        int a = idx >> 6, p = idx & 63, e = 2 * p;
        g_W2Tb[a * 64 + p] = bfpack(W2[e * A_ + a], W2[(e + 1) * A_ + a]);
    }
}

// qw for 32 batch rows per block; W1c staged once in smem
__global__ __launch_bounds__(256) void prep_qw2(const float* __restrict__ query,
                                                const float* __restrict__ b1) {
    extern __shared__ float w[];               // [E_][A_]
    __shared__ float qsh[32 * E_];
    int b0 = blockIdx.x * 32;
    for (int i = threadIdx.x; i < E_ * A_ / 4; i += 256)
        ((float4*)w)[i] = ((const float4*)g_W1c)[i];
    for (int i = threadIdx.x; i < 32 * E_ / 4; i += 256)
        ((float4*)qsh)[i] = ((const float4*)(query + (size_t)b0 * E_))[i];
    __syncthreads();
    int r = threadIdx.x >> 3;
    int a0 = (threadIdx.x & 7) * 4;
    float acc[4][4];
#pragma unroll
    for (int j = 0; j < 4; j++)
#pragma unroll
        for (int i = 0; i < 4; i++) acc[j][i] = b1[a0 + 32 * j + i];
#pragma unroll 4
    for (int e = 0; e < E_; e++) {
        float qv = qsh[r * E_ + e];
#pragma unroll
        for (int j = 0; j < 4; j++) {
            float4 wv = *(const float4*)&w[e * A_ + a0 + 32 * j];
            acc[j][0] = fmaf(qv, wv.x, acc[j][0]);
            acc[j][1] = fmaf(qv, wv.y, acc[j][1]);
            acc[j][2] = fmaf(qv, wv.z, acc[j][2]);
            acc[j][3] = fmaf(qv, wv.w, acc[j][3]);
        }
    }
#pragma unroll
    for (int j = 0; j < 4; j++)
        *(float4*)&g_qw[(size_t)(b0 + r) * A_ + a0 + 32 * j] =
            make_float4(acc[j][0], acc[j][1], acc[j][2], acc[j][3]);
}

// ---------------- warp GEMM bodies (one 16-row slab each) ----------------
// GEMM1: 16 rows x 128 cols x 128 K; h1 packed straight into GEMM2 A-frags.
__device__ __forceinline__ void gemm1_slab(uint32_t AsU, uint32_t BsU,
                                           const float* __restrict__ qwv,
                                           int rowbase, int lane,
                                           uint32_t h1f[8][4]) {
    const int tig = lane & 3;
    const uint32_t aAddr = AsU +
        (uint32_t)((rowbase + (lane & 15)) * ROWB + (lane >> 4) * 16);
    const int bRow = ((lane >> 4) << 3) + (lane & 7);
    const uint32_t bAddr = BsU + (uint32_t)(bRow * ROWB + ((lane >> 3) & 1) * 16);
#pragma unroll
    for (int qh = 0; qh < 4; qh++) {
        float acc[4][4];
#pragma unroll
        for (int nt = 0; nt < 4; nt++)
#pragma unroll
            for (int j = 0; j < 4; j++) acc[nt][j] = 0.f;
#pragma unroll
        for (int kc = 0; kc < 8; kc++) {
            uint32_t a[4];
            LDSM4(a, aAddr + kc * 32);
#pragma unroll
            for (int npl = 0; npl < 2; npl++) {
                uint32_t bf[4];
                LDSM4(bf, bAddr + (qh * 32 + npl * 16) * ROWB + kc * 32);
                MMAB(acc[2 * npl],     a, bf[0], bf[1]);
                MMAB(acc[2 * npl + 1], a, bf[2], bf[3]);
            }
        }
#pragma unroll
        for (int ntl = 0; ntl < 4; ntl++) {
            int ntg = qh * 4 + ntl;
            int c0 = ntg * 8 + 2 * tig;
            float q0 = qwv[c0], q1 = qwv[c0 + 1];
            int kcg = ntg >> 1, hf = (ntg & 1) << 1;
            h1f[kcg][hf] =
                bfpack(fmaxf(acc[ntl][0] + q0, 0.f), fmaxf(acc[ntl][1] + q1, 0.f));
            h1f[kcg][hf + 1] =
                bfpack(fmaxf(acc[ntl][2] + q0, 0.f), fmaxf(acc[ntl][3] + q1, 0.f));
        }
    }
}

// GEMM2: A = h1f (registers), B = W2T in smem; fused score dot.
__device__ __forceinline__ void gemm2_slab(uint32_t BsU, const float* __restrict__ b2v,
                                           const float* __restrict__ w3v, int lane,
                                           uint32_t h1f[8][4], float rs[2]) {
    const int tig = lane & 3;
    const int bRow = ((lane >> 4) << 3) + (lane & 7);
    const uint32_t bAddr = BsU + (uint32_t)(bRow * ROWB + ((lane >> 3) & 1) * 16);
#pragma unroll
    for (int qh = 0; qh < 4; qh++) {
        float acc[4][4];
#pragma unroll
        for (int nt = 0; nt < 4; nt++)
#pragma unroll
            for (int j = 0; j < 4; j++) acc[nt][j] = 0.f;
#pragma unroll
        for (int kc = 0; kc < 8; kc++) {
#pragma unroll
            for (int npl = 0; npl < 2; npl++) {
                uint32_t bf[4];
                LDSM4(bf, bAddr + (qh * 32 + npl * 16) * ROWB + kc * 32);
                MMAB(acc[2 * npl],     h1f[kc], bf[0], bf[1]);
                MMAB(acc[2 * npl + 1], h1f[kc], bf[2], bf[3]);
            }
        }
#pragma unroll
        for (int ntl = 0; ntl < 4; ntl++) {
            int c0 = qh * 32 + ntl * 8 + 2 * tig;
            float b20 = b2v[c0], b21 = b2v[c0 + 1];
            float w30 = w3v[c0], w31 = w3v[c0 + 1];
            rs[0] = fmaf(fmaxf(acc[ntl][0] + b20, 0.f), w30,
                    fmaf(fmaxf(acc[ntl][1] + b21, 0.f), w31, rs[0]));
            rs[1] = fmaf(fmaxf(acc[ntl][2] + b20, 0.f), w30,
                    fmaf(fmaxf(acc[ntl][3] + b21, 0.f), w31, rs[1]));
        }
    }
}

// ---------------- main kernel ----------------
__global__ __launch_bounds__(256, 2) void din_main(
    const float* __restrict__ query,
    const float* __restrict__ keys,
    const void*  __restrict__ len_ptr,
    const float* __restrict__ pos,
    const float* __restrict__ b2,
    const float* __restrict__ W3,
    const float* __restrict__ b3,
    float* __restrict__ out)
{
    extern __shared__ char sm[];
    uint32_t* As32 = (uint32_t*)(sm + OFF_AS);
    uint32_t* Bs32 = (uint32_t*)(sm + OFF_BS);
    Misc*     m    = (Misc*)(sm + OFF_MS);
    const uint32_t AsU = smem_u32(sm + OFF_AS);
    const uint32_t BsU = smem_u32(sm + OFF_BS);

    const int b = blockIdx.x;
    const int tid = threadIdx.x;
    const int wid = tid >> 5;
    const int lane = tid & 31;
    const int g = lane >> 2;
    const int tig = lane & 3;

    // keys_length dtype sniff (values in [1, L])
    unsigned long long first8 = *(const unsigned long long*)len_ptr;
    int len = (first8 <= (unsigned long long)L_)
            ? (int)((const long long*)len_ptr)[b]
            : ((const int*)len_ptr)[b];
    const int nsl = (len + 15) >> 4;          // active 16-row slabs
    const int nrows = nsl << 4;               // rows to build (<= 208)

    if (tid < 128) {
        m->qv[tid]  = query[(size_t)b * E_ + tid];
        m->qwv[tid] = g_qw[(size_t)b * A_ + tid];
        m->b2v[tid] = b2[tid];
        m->w3v[tid] = W3[tid];
    }
    __syncthreads();

    // ---- build As = bf16(keys+pos) only for active rows; Bs = bf16(Wc) ----
    {
        const float4* k4 = (const float4*)(keys + (size_t)b * L_ * E_);
        const float4* p4 = (const float4*)pos;
        for (int idx = tid; idx < nrows * 32; idx += 256) {
            int l = idx >> 5, c4 = idx & 31, e0 = c4 * 4;
            if (l < len) {
                float4 kv = k4[l * 32 + c4], pv = p4[l * 32 + c4];
                As32[l * ROWU + (e0 >> 1)]     = bfpack(kv.x + pv.x, kv.y + pv.y);
                As32[l * ROWU + (e0 >> 1) + 1] = bfpack(kv.z + pv.z, kv.w + pv.w);
            } else {
                As32[l * ROWU + (e0 >> 1)]     = 0u;
                As32[l * ROWU + (e0 >> 1) + 1] = 0u;
            }
        }
        const float4* wk4 = (const float4*)g_WkT;
        const float4* wm4 = (const float4*)g_WmT;
        for (int idx = tid; idx < 128 * 32; idx += 256) {
            int a = idx >> 5, c4 = idx & 31, e0 = c4 * 4;
            float4 wk = wk4[a * 32 + c4], wm = wm4[a * 32 + c4];
            float4 qe = *(const float4*)&m->qv[e0];
            Bs32[a * ROWU + (e0 >> 1)] =
                bfpack(fmaf(qe.x, wm.x, wk.x), fmaf(qe.y, wm.y, wk.y));
            Bs32[a * ROWU + (e0 >> 1) + 1] =
                bfpack(fmaf(qe.z, wm.z, wk.z), fmaf(qe.w, wm.w, wk.w));
        }
    }
    __syncthreads();

    // ---- GEMM1 over active slabs only (warp w owns slabs w and w+8) ----
    uint32_t h1f[2][8][4];
    const int s0 = wid, s1 = wid + 8;
    if (s0 < nsl) gemm1_slab(AsU, BsU, m->qwv, s0 * 16, lane, h1f[0]);
    if (s1 < nsl) gemm1_slab(AsU, BsU, m->qwv, s1 * 16, lane, h1f[1]);
    __syncthreads();                     // all warps done reading Bs (Wc)

    // overwrite Bs with pre-packed bf16 W2T
    {
        const uint4* src = (const uint4*)g_W2Tb;
        uint4* dst = (uint4*)Bs32;
        for (int idx = tid; idx < 128 * 16; idx += 256) {
            int row = idx >> 4, c = idx & 15;
            dst[row * 17 + c] = src[row * 16 + c];
        }
    }
    __syncthreads();

    // ---- GEMM2 + score epilogue over active slabs ----
    {
        float rs[4] = {0.f, 0.f, 0.f, 0.f};
        if (s0 < nsl) gemm2_slab(BsU, m->b2v, m->w3v, lane, h1f[0], rs);
        if (s1 < nsl) gemm2_slab(BsU, m->b2v, m->w3v, lane, h1f[1], rs + 2);
#pragma unroll
        for (int i = 0; i < 4; i++) {
            rs[i] += __shfl_xor_sync(0xffffffffu, rs[i], 1);
            rs[i] += __shfl_xor_sync(0xffffffffu, rs[i], 2);
        }
        if (tig == 0) {
            float b3v = b3[0];
            if (s0 < nsl) {
                m->scores[s0 * 16 + g]     = rs[0] + b3v;
                m->scores[s0 * 16 + 8 + g] = rs[1] + b3v;
            }
            if (s1 < nsl) {
                m->scores[s1 * 16 + g]     = rs[2] + b3v;
                m->scores[s1 * 16 + 8 + g] = rs[3] + b3v;
            }
        }
    }
    __syncthreads();

    // ---- softmax over valid l ----
    {
        int l = tid;
        bool valid = l < len;
        float sc = valid ? m->scores[l] : -1e30f;
        float mx = sc;
#pragma unroll
        for (int off = 16; off >= 1; off >>= 1)
            mx = fmaxf(mx, __shfl_xor_sync(0xffffffffu, mx, off));
        if (lane == 0) m->red[wid] = mx;
        __syncthreads();
        if (tid == 0) {
            float M = m->red[0];
            for (int i = 1; i < 8; i++) M = fmaxf(M, m->red[i]);
            m->red[8] = M;
        }
        __syncthreads();
        float M = m->red[8];
        float w = valid ? __expf(sc - M) : 0.f;
        float sum = w;
#pragma unroll
        for (int off = 16; off >= 1; off >>= 1)
            sum += __shfl_xor_sync(0xffffffffu, sum, off);
        if (lane == 0) m->red[wid] = sum;
        __syncthreads();
        if (tid == 0) {
            float S = 0.f;
            for (int i = 0; i < 8; i++) S += m->red[i];
            m->red[9] = S;
        }
        __syncthreads();
        m->wts[l] = w / m->red[9];
    }
    __syncthreads();

    // ---- out[e] = sum_{l<len} wts[l] * (keys[b][l][e] + pos[l][e]) ----
    {
        int e = tid & 127, half = tid >> 7;
        const float* kb = keys + (size_t)b * L_ * E_ + e;
        const float* pb = pos + e;
        int mid = (len + 1) >> 1;
        int l0 = half ? mid : 0;
        int l1 = half ? len : mid;
        float accO = 0.f;
#pragma unroll 4
        for (int l = l0; l < l1; l++)
            accO = fmaf(m->wts[l], __ldg(&kb[(size_t)l * E_]) + pb[(size_t)l * E_], accO);
        m->po[half * 128 + e] = accO;
    }
    __syncthreads();
    if (tid < 128)
        out[(size_t)b * E_ + tid] = m->po[tid] + m->po[128 + tid];
}

// ---------------- entry ----------------
extern "C" void kernel_launch(void* const* d_in, const int* in_sizes, int n_in,
                              void* d_out, int out_size) {
    const float* query = (const float*)d_in[0];
    const float* keys  = (const float*)d_in[1];
    const void*  klen  = d_in[2];
    const float* pos   = (const float*)d_in[3];
    const float* W1    = (const float*)d_in[4];
    const float* b1    = (const float*)d_in[5];
    const float* W2    = (const float*)d_in[6];
    const float* b2    = (const float*)d_in[7];
    const float* W3    = (const float*)d_in[8];
    const float* b3    = (const float*)d_in[9];
    float* out = (float*)d_out;
    (void)in_sizes; (void)n_in; (void)out_size;

    cudaFuncSetAttribute(din_main, cudaFuncAttributeMaxDynamicSharedMemorySize,
                         SMEM_TOTAL);
    cudaFuncSetAttribute(prep_qw2, cudaFuncAttributeMaxDynamicSharedMemorySize,
                         E_ * A_ * 4);

    prep_wt<<<(A_ * E_ + 255) / 256, 256>>>(W1, W2);
    prep_qw2<<<B_ / 32, 256, E_ * A_ * 4>>>(query, b1);
    din_main<<<B_, 256, SMEM_TOTAL>>>(query, keys, klen, pos, b2, W3, b3, out);
}

// round 8
// speedup vs baseline: 18.2714x; 1.0634x over previous
#include <cuda_runtime.h>
#include <cstdint>

#define B_ 4096
#define L_ 200
#define E_ 128
#define A_ 128
#define MRp 208             // max 13 slabs x 16 rows
#define ROWB 272            // bytes per bf16 row (17 x 16B -> conflict-free ldmatrix)
#define ROWU 68             // uint32 per row

// dynamic smem layout
#define OFF_AS 0                         // bf16 As[208][136] = 56576 B (kp only)
#define OFF_BS 56576                     // bf16 Bs[128][136] = 34816 B (Wc, then W2T)
#define OFF_MS 91392
struct Misc {
    float qwv[A_], b2v[A_], w3v[A_];
    uint32_t qb[64];                     // bf16x2-packed query pairs
    float scores[256], wts[256];
    float red[16], po[256];
};
#define SMEM_TOTAL (OFF_MS + (int)sizeof(Misc))   // ~96.3 KB -> 2 CTAs/SM

// Global scratch (allocation forbidden)
__device__ float    g_qw[B_ * A_];       // q @ (W1q + W1d) + b1
__device__ float    g_W1c[E_ * A_];      // W1q + W1d   [e][a]
__device__ uint32_t g_Wkb[A_ * 64];      // bf16x2 (W1k - W1d)^T pairs [a][e/2]
__device__ uint32_t g_Wmb[A_ * 64];      // bf16x2 W1m^T pairs         [a][e/2]
__device__ uint32_t g_W2Tb[A_ * A_ / 2]; // W2^T bf16 pairs [aout][ain/2]

__device__ __forceinline__ uint32_t smem_u32(const void* p) {
    uint32_t a;
    asm("{ .reg .u64 t; cvta.to.shared.u64 t, %1; cvt.u32.u64 %0, t; }"
        : "=r"(a) : "l"(p));
    return a;
}
__device__ __forceinline__ uint32_t bfpack(float lo, float hi) {
    uint32_t r;
    asm("cvt.rn.bf16x2.f32 %0, %1, %2;" : "=r"(r) : "f"(hi), "f"(lo));
    return r;
}
__device__ __forceinline__ uint32_t bffma2(uint32_t a, uint32_t b, uint32_t c) {
    uint32_t d;   // d = a*b + c elementwise on bf16x2
    asm("fma.rn.bf16x2 %0, %1, %2, %3;" : "=r"(d) : "r"(a), "r"(b), "r"(c));
    return d;
}
#define LDSM4(r, addr)                                                         \
    asm volatile("ldmatrix.sync.aligned.m8n8.x4.shared.b16 {%0,%1,%2,%3}, [%4];" \
                 : "=r"((r)[0]), "=r"((r)[1]), "=r"((r)[2]), "=r"((r)[3])      \
                 : "r"(addr))
#define MMAB(d, a, b0, b1)                                                     \
    asm volatile("mma.sync.aligned.m16n8k16.row.col.f32.bf16.bf16.f32 "        \
                 "{%0,%1,%2,%3}, {%4,%5,%6,%7}, {%8,%9}, {%0,%1,%2,%3};"       \
                 : "+f"((d)[0]), "+f"((d)[1]), "+f"((d)[2]), "+f"((d)[3])      \
                 : "r"((a)[0]), "r"((a)[1]), "r"((a)[2]), "r"((a)[3]),         \
                   "r"(b0), "r"(b1))

// ---------------- prep kernels ----------------
__global__ void prep_wt(const float* __restrict__ W1, const float* __restrict__ W2) {
    int idx = blockIdx.x * blockDim.x + threadIdx.x;
    if (idx < A_ * E_) {
        g_W1c[idx] = W1[idx] + W1[2 * E_ * A_ + idx];
    }
    if (idx < A_ * 64) {                 // bf16x2 pairs for Wk, Wm
        int a = idx >> 6, p = idx & 63, e = 2 * p;
        float wk0 = W1[(E_ + e) * A_ + a]     - W1[(2 * E_ + e) * A_ + a];
        float wk1 = W1[(E_ + e + 1) * A_ + a] - W1[(2 * E_ + e + 1) * A_ + a];
        g_Wkb[idx] = bfpack(wk0, wk1);
        g_Wmb[idx] = bfpack(W1[(3 * E_ + e) * A_ + a], W1[(3 * E_ + e + 1) * A_ + a]);
    }
    if (idx < A_ * A_ / 2) {
        int a = idx >> 6, p = idx & 63, e = 2 * p;
        g_W2Tb[idx] = bfpack(W2[e * A_ + a], W2[(e + 1) * A_ + a]);
    }
}

// qw for 32 batch rows per block; W1c staged once in smem
__global__ __launch_bounds__(256) void prep_qw2(const float* __restrict__ query,
                                                const float* __restrict__ b1) {
    extern __shared__ float w[];               // [E_][A_]
    __shared__ float qsh[32 * E_];
    int b0 = blockIdx.x * 32;
    for (int i = threadIdx.x; i < E_ * A_ / 4; i += 256)
        ((float4*)w)[i] = ((const float4*)g_W1c)[i];
    for (int i = threadIdx.x; i < 32 * E_ / 4; i += 256)
        ((float4*)qsh)[i] = ((const float4*)(query + (size_t)b0 * E_))[i];
    __syncthreads();
    int r = threadIdx.x >> 3;
    int a0 = (threadIdx.x & 7) * 4;
    float acc[4][4];
#pragma unroll
    for (int j = 0; j < 4; j++)
#pragma unroll
        for (int i = 0; i < 4; i++) acc[j][i] = b1[a0 + 32 * j + i];
#pragma unroll 4
    for (int e = 0; e < E_; e++) {
        float qv = qsh[r * E_ + e];
#pragma unroll
        for (int j = 0; j < 4; j++) {
            float4 wv = *(const float4*)&w[e * A_ + a0 + 32 * j];
            acc[j][0] = fmaf(qv, wv.x, acc[j][0]);
            acc[j][1] = fmaf(qv, wv.y, acc[j][1]);
            acc[j][2] = fmaf(qv, wv.z, acc[j][2]);
            acc[j][3] = fmaf(qv, wv.w, acc[j][3]);
        }
    }
#pragma unroll
    for (int j = 0; j < 4; j++)
        *(float4*)&g_qw[(size_t)(b0 + r) * A_ + a0 + 32 * j] =
            make_float4(acc[j][0], acc[j][1], acc[j][2], acc[j][3]);
}

// ---------------- warp GEMM bodies (one 16-row slab each) ----------------
__device__ __forceinline__ void gemm1_slab(uint32_t AsU, uint32_t BsU,
                                           const float* __restrict__ qwv,
                                           int rowbase, int lane,
                                           uint32_t h1f[8][4]) {
    const int tig = lane & 3;
    const uint32_t aAddr = AsU +
        (uint32_t)((rowbase + (lane & 15)) * ROWB + (lane >> 4) * 16);
    const int bRow = ((lane >> 4) << 3) + (lane & 7);
    const uint32_t bAddr = BsU + (uint32_t)(bRow * ROWB + ((lane >> 3) & 1) * 16);
#pragma unroll
    for (int qh = 0; qh < 4; qh++) {
        float acc[4][4];
#pragma unroll
        for (int nt = 0; nt < 4; nt++)
#pragma unroll
            for (int j = 0; j < 4; j++) acc[nt][j] = 0.f;
#pragma unroll
        for (int kc = 0; kc < 8; kc++) {
            uint32_t a[4];
            LDSM4(a, aAddr + kc * 32);
#pragma unroll
            for (int npl = 0; npl < 2; npl++) {
                uint32_t bf[4];
                LDSM4(bf, bAddr + (qh * 32 + npl * 16) * ROWB + kc * 32);
                MMAB(acc[2 * npl],     a, bf[0], bf[1]);
                MMAB(acc[2 * npl + 1], a, bf[2], bf[3]);
            }
        }
#pragma unroll
        for (int ntl = 0; ntl < 4; ntl++) {
            int ntg = qh * 4 + ntl;
            int c0 = ntg * 8 + 2 * tig;
            float q0 = qwv[c0], q1 = qwv[c0 + 1];
            int kcg = ntg >> 1, hf = (ntg & 1) << 1;
            h1f[kcg][hf] =
                bfpack(fmaxf(acc[ntl][0] + q0, 0.f), fmaxf(acc[ntl][1] + q1, 0.f));
            h1f[kcg][hf + 1] =
                bfpack(fmaxf(acc[ntl][2] + q0, 0.f), fmaxf(acc[ntl][3] + q1, 0.f));
        }
    }
}

__device__ __forceinline__ void gemm2_slab(uint32_t BsU, const float* __restrict__ b2v,
                                           const float* __restrict__ w3v, int lane,
                                           uint32_t h1f[8][4], float rs[2]) {
    const int tig = lane & 3;
    const int bRow = ((lane >> 4) << 3) + (lane & 7);
    const uint32_t bAddr = BsU + (uint32_t)(bRow * ROWB + ((lane >> 3) & 1) * 16);
#pragma unroll
    for (int qh = 0; qh < 4; qh++) {
        float acc[4][4];
#pragma unroll
        for (int nt = 0; nt < 4; nt++)
#pragma unroll
            for (int j = 0; j < 4; j++) acc[nt][j] = 0.f;
#pragma unroll
        for (int kc = 0; kc < 8; kc++) {
#pragma unroll
            for (int npl = 0; npl < 2; npl++) {
                uint32_t bf[4];
                LDSM4(bf, bAddr + (qh * 32 + npl * 16) * ROWB + kc * 32);
                MMAB(acc[2 * npl],     h1f[kc], bf[0], bf[1]);
                MMAB(acc[2 * npl + 1], h1f[kc], bf[2], bf[3]);
            }
        }
#pragma unroll
        for (int ntl = 0; ntl < 4; ntl++) {
            int c0 = qh * 32 + ntl * 8 + 2 * tig;
            float b20 = b2v[c0], b21 = b2v[c0 + 1];
            float w30 = w3v[c0], w31 = w3v[c0 + 1];
            rs[0] = fmaf(fmaxf(acc[ntl][0] + b20, 0.f), w30,
                    fmaf(fmaxf(acc[ntl][1] + b21, 0.f), w31, rs[0]));
            rs[1] = fmaf(fmaxf(acc[ntl][2] + b20, 0.f), w30,
                    fmaf(fmaxf(acc[ntl][3] + b21, 0.f), w31, rs[1]));
        }
    }
}

// ---------------- main kernel ----------------
__global__ __launch_bounds__(256, 2) void din_main(
    const float* __restrict__ query,
    const float* __restrict__ keys,
    const void*  __restrict__ len_ptr,
    const float* __restrict__ pos,
    const float* __restrict__ b2,
    const float* __restrict__ W3,
    const float* __restrict__ b3,
    float* __restrict__ out)
{
    extern __shared__ char sm[];
    uint32_t* As32 = (uint32_t*)(sm + OFF_AS);
    uint32_t* Bs32 = (uint32_t*)(sm + OFF_BS);
    Misc*     m    = (Misc*)(sm + OFF_MS);
    const uint32_t AsU = smem_u32(sm + OFF_AS);
    const uint32_t BsU = smem_u32(sm + OFF_BS);

    const int b = blockIdx.x;
    const int tid = threadIdx.x;
    const int wid = tid >> 5;
    const int lane = tid & 31;
    const int g = lane >> 2;
    const int tig = lane & 3;

    // keys_length dtype sniff (values in [1, L])
    unsigned long long first8 = *(const unsigned long long*)len_ptr;
    int len = (first8 <= (unsigned long long)L_)
            ? (int)((const long long*)len_ptr)[b]
            : ((const int*)len_ptr)[b];
    const int nsl = (len + 15) >> 4;          // active 16-row slabs
    const int nrows = nsl << 4;

    if (tid < 128) {
        m->qwv[tid] = g_qw[(size_t)b * A_ + tid];
        m->b2v[tid] = b2[tid];
        m->w3v[tid] = W3[tid];
    }
    if (tid < 64) {                           // bf16x2-packed q pairs (from global)
        float2 qf = ((const float2*)query)[(size_t)b * 64 + tid];
        m->qb[tid] = bfpack(qf.x, qf.y);
    }
    __syncthreads();

    // ---- build As = bf16(keys+pos) for active rows; Bs = Wc via bf16x2 fma ----
    {
        const float4* k4 = (const float4*)(keys + (size_t)b * L_ * E_);
        const float4* p4 = (const float4*)pos;
        for (int idx = tid; idx < nrows * 32; idx += 256) {
            int l = idx >> 5, c4 = idx & 31, e0 = c4 * 4;
            if (l < len) {
                float4 kv = k4[l * 32 + c4], pv = p4[l * 32 + c4];
                As32[l * ROWU + (e0 >> 1)]     = bfpack(kv.x + pv.x, kv.y + pv.y);
                As32[l * ROWU + (e0 >> 1) + 1] = bfpack(kv.z + pv.z, kv.w + pv.w);
            } else {
                As32[l * ROWU + (e0 >> 1)]     = 0u;
                As32[l * ROWU + (e0 >> 1) + 1] = 0u;
            }
        }
        const uint2* wk2 = (const uint2*)g_Wkb;
        const uint2* wm2 = (const uint2*)g_Wmb;
        const uint2* qb2 = (const uint2*)m->qb;
        for (int idx = tid; idx < 128 * 32; idx += 256) {
            int a = idx >> 5, u2 = idx & 31;
            uint2 wk = wk2[a * 32 + u2];
            uint2 wm = wm2[a * 32 + u2];
            uint2 qq = qb2[u2];
            uint2 r;
            r.x = bffma2(qq.x, wm.x, wk.x);
            r.y = bffma2(qq.y, wm.y, wk.y);
            *(uint2*)&Bs32[a * ROWU + 2 * u2] = r;
        }
    }
    __syncthreads();

    // ---- GEMM1 over active slabs only (warp w owns slabs w and w+8) ----
    uint32_t h1f[2][8][4];
    const int s0 = wid, s1 = wid + 8;
    if (s0 < nsl) gemm1_slab(AsU, BsU, m->qwv, s0 * 16, lane, h1f[0]);
    if (s1 < nsl) gemm1_slab(AsU, BsU, m->qwv, s1 * 16, lane, h1f[1]);
    __syncthreads();                     // all warps done reading Bs (Wc)

    // overwrite Bs with pre-packed bf16 W2T
    {
        const uint4* src = (const uint4*)g_W2Tb;
        uint4* dst = (uint4*)Bs32;
        for (int idx = tid; idx < 128 * 16; idx += 256) {
            int row = idx >> 4, c = idx & 15;
            dst[row * 17 + c] = src[row * 16 + c];
        }
    }
    __syncthreads();

    // ---- GEMM2 + score epilogue over active slabs ----
    {
        float rs[4] = {0.f, 0.f, 0.f, 0.f};
        if (s0 < nsl) gemm2_slab(BsU, m->b2v, m->w3v, lane, h1f[0], rs);
        if (s1 < nsl) gemm2_slab(BsU, m->b2v, m->w3v, lane, h1f[1], rs + 2);
#pragma unroll
        for (int i = 0; i < 4; i++) {
            rs[i] += __shfl_xor_sync(0xffffffffu, rs[i], 1);
            rs[i] += __shfl_xor_sync(0xffffffffu, rs[i], 2);
        }
        if (tig == 0) {
            float b3v = b3[0];
            if (s0 < nsl) {
                m->scores[s0 * 16 + g]     = rs[0] + b3v;
                m->scores[s0 * 16 + 8 + g] = rs[1] + b3v;
            }
            if (s1 < nsl) {
                m->scores[s1 * 16 + g]     = rs[2] + b3v;
                m->scores[s1 * 16 + 8 + g] = rs[3] + b3v;
            }
        }
    }
    __syncthreads();

    // ---- softmax over valid l ----
    {
        int l = tid;
        bool valid = l < len;
        float sc = valid ? m->scores[l] : -1e30f;
        float mx = sc;
#pragma unroll
        for (int off = 16; off >= 1; off >>= 1)
            mx = fmaxf(mx, __shfl_xor_sync(0xffffffffu, mx, off));
        if (lane == 0) m->red[wid] = mx;
        __syncthreads();
        if (tid == 0) {
            float M = m->red[0];
            for (int i = 1; i < 8; i++) M = fmaxf(M, m->red[i]);
            m->red[8] = M;
        }
        __syncthreads();
        float M = m->red[8];
        float w = valid ? __expf(sc - M) : 0.f;
        float sum = w;
#pragma unroll
        for (int off = 16; off >= 1; off >>= 1)
            sum += __shfl_xor_sync(0xffffffffu, sum, off);
        if (lane == 0) m->red[wid] = sum;
        __syncthreads();
        if (tid == 0) {
            float S = 0.f;
            for (int i = 0; i < 8; i++) S += m->red[i];
            m->red[9] = S;
        }
        __syncthreads();
        m->wts[l] = w / m->red[9];
    }
    __syncthreads();

    // ---- out[e] = sum_{l<len} wts[l] * (keys[b][l][e] + pos[l][e]) ----
    {
        int e = tid & 127, half = tid >> 7;
        const float* kb = keys + (size_t)b * L_ * E_ + e;
        const float* pb = pos + e;
        int mid = (len + 1) >> 1;
        int l0 = half ? mid : 0;
        int l1 = half ? len : mid;
        float a0 = 0.f, a1 = 0.f, a2 = 0.f, a3 = 0.f;
        int l = l0;
        for (; l + 3 < l1; l += 4) {
            a0 = fmaf(m->wts[l],     __ldg(&kb[(size_t)l * E_])       + pb[(size_t)l * E_],       a0);
            a1 = fmaf(m->wts[l + 1], __ldg(&kb[(size_t)(l + 1) * E_]) + pb[(size_t)(l + 1) * E_], a1);
            a2 = fmaf(m->wts[l + 2], __ldg(&kb[(size_t)(l + 2) * E_]) + pb[(size_t)(l + 2) * E_], a2);
            a3 = fmaf(m->wts[l + 3], __ldg(&kb[(size_t)(l + 3) * E_]) + pb[(size_t)(l + 3) * E_], a3);
        }
        for (; l < l1; l++)
            a0 = fmaf(m->wts[l], __ldg(&kb[(size_t)l * E_]) + pb[(size_t)l * E_], a0);
        m->po[half * 128 + e] = (a0 + a1) + (a2 + a3);
    }
    __syncthreads();
    if (tid < 128)
        out[(size_t)b * E_ + tid] = m->po[tid] + m->po[128 + tid];
}

// ---------------- entry ----------------
extern "C" void kernel_launch(void* const* d_in, const int* in_sizes, int n_in,
                              void* d_out, int out_size) {
    const float* query = (const float*)d_in[0];
    const float* keys  = (const float*)d_in[1];
    const void*  klen  = d_in[2];
    const float* pos   = (const float*)d_in[3];
    const float* W1    = (const float*)d_in[4];
    const float* b1    = (const float*)d_in[5];
    const float* W2    = (const float*)d_in[6];
    const float* b2    = (const float*)d_in[7];
    const float* W3    = (const float*)d_in[8];
    const float* b3    = (const float*)d_in[9];
    float* out = (float*)d_out;
    (void)in_sizes; (void)n_in; (void)out_size;

    cudaFuncSetAttribute(din_main, cudaFuncAttributeMaxDynamicSharedMemorySize,
                         SMEM_TOTAL);
    cudaFuncSetAttribute(prep_qw2, cudaFuncAttributeMaxDynamicSharedMemorySize,
                         E_ * A_ * 4);

    prep_wt<<<(A_ * E_ + 255) / 256, 256>>>(W1, W2);
    prep_qw2<<<B_ / 32, 256, E_ * A_ * 4>>>(query, b1);
    din_main<<<B_, 256, SMEM_TOTAL>>>(query, keys, klen, pos, b2, W3, b3, out);
}

// round 9
// speedup vs baseline: 19.2272x; 1.0523x over previous
#include <cuda_runtime.h>
#include <cstdint>

#define B_ 4096
#define L_ 200
#define E_ 128
#define A_ 128
#define MRp 208             // max 13 slabs x 16 rows
#define ROWB 272            // bytes per bf16 row (17 x 16B -> conflict-free ldmatrix)
#define ROWU 68             // uint32 per row

// dynamic smem layout
#define OFF_AS 0                         // bf16 As[208][136] = 56576 B (kp only)
#define OFF_BS 56576                     // bf16 Bs[128][136] = 34816 B (Wc, then W2T)
#define OFF_MS 91392
struct Misc {
    float qwv[A_], b2v[A_], w3v[A_];
    uint32_t qb[64];                     // bf16x2-packed query pairs
    float scores[256], wts[256];
    float red[16], po[256];
};
#define SMEM_TOTAL (OFF_MS + (int)sizeof(Misc))   // ~96.3 KB -> 2 CTAs/SM

// Global scratch (allocation forbidden)
__device__ float    g_qw[B_ * A_];       // q @ (W1q + W1d) + b1
__device__ float    g_W1c[E_ * A_];      // W1q + W1d   [e][a]
__device__ uint32_t g_Wkb[A_ * 64];      // bf16x2 (W1k - W1d)^T pairs [a][e/2]
__device__ uint32_t g_Wmb[A_ * 64];      // bf16x2 W1m^T pairs         [a][e/2]
__device__ uint32_t g_W2Tb[A_ * A_ / 2]; // W2^T bf16 pairs [aout][ain/2]

__device__ __forceinline__ uint32_t smem_u32(const void* p) {
    uint32_t a;
    asm("{ .reg .u64 t; cvta.to.shared.u64 t, %1; cvt.u32.u64 %0, t; }"
        : "=r"(a) : "l"(p));
    return a;
}
__device__ __forceinline__ uint32_t bfpack(float lo, float hi) {
    uint32_t r;
    asm("cvt.rn.bf16x2.f32 %0, %1, %2;" : "=r"(r) : "f"(hi), "f"(lo));
    return r;
}
__device__ __forceinline__ uint32_t bffma2(uint32_t a, uint32_t b, uint32_t c) {
    uint32_t d;
    asm("fma.rn.bf16x2 %0, %1, %2, %3;" : "=r"(d) : "r"(a), "r"(b), "r"(c));
    return d;
}
#define LDSM4(r, addr)                                                         \
    asm volatile("ldmatrix.sync.aligned.m8n8.x4.shared.b16 {%0,%1,%2,%3}, [%4];" \
                 : "=r"((r)[0]), "=r"((r)[1]), "=r"((r)[2]), "=r"((r)[3])      \
                 : "r"(addr))
#define MMAB(d, a, b0, b1)                                                     \
    asm volatile("mma.sync.aligned.m16n8k16.row.col.f32.bf16.bf16.f32 "        \
                 "{%0,%1,%2,%3}, {%4,%5,%6,%7}, {%8,%9}, {%0,%1,%2,%3};"       \
                 : "+f"((d)[0]), "+f"((d)[1]), "+f"((d)[2]), "+f"((d)[3])      \
                 : "r"((a)[0]), "r"((a)[1]), "r"((a)[2]), "r"((a)[3]),         \
                   "r"(b0), "r"(b1))

// ---------------- prep kernels ----------------
__global__ void prep_wt(const float* __restrict__ W1, const float* __restrict__ W2) {
    int idx = blockIdx.x * blockDim.x + threadIdx.x;
    if (idx < A_ * E_) {
        g_W1c[idx] = W1[idx] + W1[2 * E_ * A_ + idx];
    }
    if (idx < A_ * 64) {
        int a = idx >> 6, p = idx & 63, e = 2 * p;
        float wk0 = W1[(E_ + e) * A_ + a]     - W1[(2 * E_ + e) * A_ + a];
        float wk1 = W1[(E_ + e + 1) * A_ + a] - W1[(2 * E_ + e + 1) * A_ + a];
        g_Wkb[idx] = bfpack(wk0, wk1);
        g_Wmb[idx] = bfpack(W1[(3 * E_ + e) * A_ + a], W1[(3 * E_ + e + 1) * A_ + a]);
    }
    if (idx < A_ * A_ / 2) {
        int a = idx >> 6, p = idx & 63, e = 2 * p;
        g_W2Tb[idx] = bfpack(W2[e * A_ + a], W2[(e + 1) * A_ + a]);
    }
}

__global__ __launch_bounds__(256) void prep_qw2(const float* __restrict__ query,
                                                const float* __restrict__ b1) {
    extern __shared__ float w[];
    __shared__ float qsh[32 * E_];
    int b0 = blockIdx.x * 32;
    for (int i = threadIdx.x; i < E_ * A_ / 4; i += 256)
        ((float4*)w)[i] = ((const float4*)g_W1c)[i];
    for (int i = threadIdx.x; i < 32 * E_ / 4; i += 256)
        ((float4*)qsh)[i] = ((const float4*)(query + (size_t)b0 * E_))[i];
    __syncthreads();
    int r = threadIdx.x >> 3;
    int a0 = (threadIdx.x & 7) * 4;
    float acc[4][4];
#pragma unroll
    for (int j = 0; j < 4; j++)
#pragma unroll
        for (int i = 0; i < 4; i++) acc[j][i] = b1[a0 + 32 * j + i];
#pragma unroll 4
    for (int e = 0; e < E_; e++) {
        float qv = qsh[r * E_ + e];
#pragma unroll
        for (int j = 0; j < 4; j++) {
            float4 wv = *(const float4*)&w[e * A_ + a0 + 32 * j];
            acc[j][0] = fmaf(qv, wv.x, acc[j][0]);
            acc[j][1] = fmaf(qv, wv.y, acc[j][1]);
            acc[j][2] = fmaf(qv, wv.z, acc[j][2]);
            acc[j][3] = fmaf(qv, wv.w, acc[j][3]);
        }
    }
#pragma unroll
    for (int j = 0; j < 4; j++)
        *(float4*)&g_qw[(size_t)(b0 + r) * A_ + a0 + 32 * j] =
            make_float4(acc[j][0], acc[j][1], acc[j][2], acc[j][3]);
}

// ---------------- warp GEMM bodies (one 16-row slab each) ----------------
__device__ __forceinline__ void gemm1_slab(uint32_t AsU, uint32_t BsU,
                                           const float* __restrict__ qwv,
                                           int rowbase, int lane,
                                           uint32_t h1f[8][4]) {
    const int tig = lane & 3;
    const uint32_t aAddr = AsU +
        (uint32_t)((rowbase + (lane & 15)) * ROWB + (lane >> 4) * 16);
    const int bRow = ((lane >> 4) << 3) + (lane & 7);
    const uint32_t bAddr = BsU + (uint32_t)(bRow * ROWB + ((lane >> 3) & 1) * 16);
#pragma unroll
    for (int qh = 0; qh < 4; qh++) {
        float acc[4][4];
#pragma unroll
        for (int nt = 0; nt < 4; nt++)
#pragma unroll
            for (int j = 0; j < 4; j++) acc[nt][j] = 0.f;
#pragma unroll
        for (int kc = 0; kc < 8; kc++) {
            uint32_t a[4];
            LDSM4(a, aAddr + kc * 32);
#pragma unroll
            for (int npl = 0; npl < 2; npl++) {
                uint32_t bf[4];
                LDSM4(bf, bAddr + (qh * 32 + npl * 16) * ROWB + kc * 32);
                MMAB(acc[2 * npl],     a, bf[0], bf[1]);
                MMAB(acc[2 * npl + 1], a, bf[2], bf[3]);
            }
        }
#pragma unroll
        for (int ntl = 0; ntl < 4; ntl++) {
            int ntg = qh * 4 + ntl;
            int c0 = ntg * 8 + 2 * tig;
            float q0 = qwv[c0], q1 = qwv[c0 + 1];
            int kcg = ntg >> 1, hf = (ntg & 1) << 1;
            h1f[kcg][hf] =
                bfpack(fmaxf(acc[ntl][0] + q0, 0.f), fmaxf(acc[ntl][1] + q1, 0.f));
            h1f[kcg][hf + 1] =
                bfpack(fmaxf(acc[ntl][2] + q0, 0.f), fmaxf(acc[ntl][3] + q1, 0.f));
        }
    }
}

__device__ __forceinline__ void gemm2_slab(uint32_t BsU, const float* __restrict__ b2v,
                                           const float* __restrict__ w3v, int lane,
                                           uint32_t h1f[8][4], float rs[2]) {
    const int tig = lane & 3;
    const int bRow = ((lane >> 4) << 3) + (lane & 7);
    const uint32_t bAddr = BsU + (uint32_t)(bRow * ROWB + ((lane >> 3) & 1) * 16);
#pragma unroll
    for (int qh = 0; qh < 4; qh++) {
        float acc[4][4];
#pragma unroll
        for (int nt = 0; nt < 4; nt++)
#pragma unroll
            for (int j = 0; j < 4; j++) acc[nt][j] = 0.f;
#pragma unroll
        for (int kc = 0; kc < 8; kc++) {
#pragma unroll
            for (int npl = 0; npl < 2; npl++) {
                uint32_t bf[4];
                LDSM4(bf, bAddr + (qh * 32 + npl * 16) * ROWB + kc * 32);
                MMAB(acc[2 * npl],     h1f[kc], bf[0], bf[1]);
                MMAB(acc[2 * npl + 1], h1f[kc], bf[2], bf[3]);
            }
        }
#pragma unroll
        for (int ntl = 0; ntl < 4; ntl++) {
            int c0 = qh * 32 + ntl * 8 + 2 * tig;
            float b20 = b2v[c0], b21 = b2v[c0 + 1];
            float w30 = w3v[c0], w31 = w3v[c0 + 1];
            rs[0] = fmaf(fmaxf(acc[ntl][0] + b20, 0.f), w30,
                    fmaf(fmaxf(acc[ntl][1] + b21, 0.f), w31, rs[0]));
            rs[1] = fmaf(fmaxf(acc[ntl][2] + b20, 0.f), w30,
                    fmaf(fmaxf(acc[ntl][3] + b21, 0.f), w31, rs[1]));
        }
    }
}

// ---------------- main kernel ----------------
__global__ __launch_bounds__(256, 2) void din_main(
    const float* __restrict__ query,
    const float* __restrict__ keys,
    const void*  __restrict__ len_ptr,
    const float* __restrict__ pos,
    const float* __restrict__ b2,
    const float* __restrict__ W3,
    const float* __restrict__ b3,
    float* __restrict__ out)
{
    extern __shared__ char sm[];
    uint32_t* As32 = (uint32_t*)(sm + OFF_AS);
    uint32_t* Bs32 = (uint32_t*)(sm + OFF_BS);
    Misc*     m    = (Misc*)(sm + OFF_MS);
    const uint32_t AsU = smem_u32(sm + OFF_AS);
    const uint32_t BsU = smem_u32(sm + OFF_BS);

    const int b = blockIdx.x;
    const int tid = threadIdx.x;
    const int wid = tid >> 5;
    const int lane = tid & 31;
    const int g = lane >> 2;
    const int tig = lane & 3;

    // keys_length dtype sniff (values in [1, L])
    unsigned long long first8 = *(const unsigned long long*)len_ptr;
    int len = (first8 <= (unsigned long long)L_)
            ? (int)((const long long*)len_ptr)[b]
            : ((const int*)len_ptr)[b];
    const int nsl = (len + 15) >> 4;          // active 16-row slabs
    const int nrows = nsl << 4;

    if (tid < 128) {
        m->qwv[tid] = g_qw[(size_t)b * A_ + tid];
        m->b2v[tid] = b2[tid];
        m->w3v[tid] = W3[tid];
    }
    if (tid < 64) {
        float2 qf = ((const float2*)query)[(size_t)b * 64 + tid];
        m->qb[tid] = bfpack(qf.x, qf.y);
    }
    __syncthreads();

    // ---- build As = bf16(keys+pos) for active rows; Bs = Wc via bf16x2 fma ----
    {
        const float4* k4 = (const float4*)(keys + (size_t)b * L_ * E_);
        const float4* p4 = (const float4*)pos;
        for (int idx = tid; idx < nrows * 32; idx += 256) {
            int l = idx >> 5, c4 = idx & 31, e0 = c4 * 4;
            if (l < len) {
                float4 kv = k4[l * 32 + c4], pv = p4[l * 32 + c4];
                As32[l * ROWU + (e0 >> 1)]     = bfpack(kv.x + pv.x, kv.y + pv.y);
                As32[l * ROWU + (e0 >> 1) + 1] = bfpack(kv.z + pv.z, kv.w + pv.w);
            } else {
                As32[l * ROWU + (e0 >> 1)]     = 0u;
                As32[l * ROWU + (e0 >> 1) + 1] = 0u;
            }
        }
        const uint2* wk2 = (const uint2*)g_Wkb;
        const uint2* wm2 = (const uint2*)g_Wmb;
        const uint2* qb2 = (const uint2*)m->qb;
        for (int idx = tid; idx < 128 * 32; idx += 256) {
            int a = idx >> 5, u2 = idx & 31;
            uint2 wk = wk2[a * 32 + u2];
            uint2 wm = wm2[a * 32 + u2];
            uint2 qq = qb2[u2];
            uint2 r;
            r.x = bffma2(qq.x, wm.x, wk.x);
            r.y = bffma2(qq.y, wm.y, wk.y);
            *(uint2*)&Bs32[a * ROWU + 2 * u2] = r;
        }
    }
    __syncthreads();

    // ---- prefetch W2T into registers (L2 latency overlaps GEMM1) ----
    uint4 w2t[8];
    {
        const uint4* src = (const uint4*)g_W2Tb;
#pragma unroll
        for (int j = 0; j < 8; j++)
            w2t[j] = __ldg(&src[tid + j * 256]);
    }

    // ---- GEMM1 over active slabs only (warp w owns slabs w and w+8) ----
    uint32_t h1f[2][8][4];
    const int s0 = wid, s1 = wid + 8;
    if (s0 < nsl) gemm1_slab(AsU, BsU, m->qwv, s0 * 16, lane, h1f[0]);
    if (s1 < nsl) gemm1_slab(AsU, BsU, m->qwv, s1 * 16, lane, h1f[1]);
    __syncthreads();                     // all warps done reading Bs (Wc)

    // store prefetched W2T into Bs (pure STS)
    {
        uint4* dst = (uint4*)Bs32;
#pragma unroll
        for (int j = 0; j < 8; j++) {
            int idx = tid + j * 256;
            int row = idx >> 4, c = idx & 15;
            dst[row * 17 + c] = w2t[j];
        }
    }
    __syncthreads();

    // ---- GEMM2 + score epilogue over active slabs ----
    {
        float rs[4] = {0.f, 0.f, 0.f, 0.f};
        if (s0 < nsl) gemm2_slab(BsU, m->b2v, m->w3v, lane, h1f[0], rs);
        if (s1 < nsl) gemm2_slab(BsU, m->b2v, m->w3v, lane, h1f[1], rs + 2);
#pragma unroll
        for (int i = 0; i < 4; i++) {
            rs[i] += __shfl_xor_sync(0xffffffffu, rs[i], 1);
            rs[i] += __shfl_xor_sync(0xffffffffu, rs[i], 2);
        }
        if (tig == 0) {
            float b3v = b3[0];
            if (s0 < nsl) {
                m->scores[s0 * 16 + g]     = rs[0] + b3v;
                m->scores[s0 * 16 + 8 + g] = rs[1] + b3v;
            }
            if (s1 < nsl) {
                m->scores[s1 * 16 + g]     = rs[2] + b3v;
                m->scores[s1 * 16 + 8 + g] = rs[3] + b3v;
            }
        }
    }
    __syncthreads();

    // ---- softmax over valid l (2 barriers; every warp reduces red[] itself) ----
    {
        int l = tid;
        bool valid = l < len;
        float sc = valid ? m->scores[l] : -1e30f;
        float mx = sc;
#pragma unroll
        for (int off = 16; off >= 1; off >>= 1)
            mx = fmaxf(mx, __shfl_xor_sync(0xffffffffu, mx, off));
        if (lane == 0) m->red[wid] = mx;
        __syncthreads();
        float M = m->red[0];
#pragma unroll
        for (int i = 1; i < 8; i++) M = fmaxf(M, m->red[i]);
        float w = valid ? __expf(sc - M) : 0.f;
        float sum = w;
#pragma unroll
        for (int off = 16; off >= 1; off >>= 1)
            sum += __shfl_xor_sync(0xffffffffu, sum, off);
        if (lane == 0) m->red[8 + wid] = sum;
        __syncthreads();
        float S = 0.f;
#pragma unroll
        for (int i = 0; i < 8; i++) S += m->red[8 + i];
        m->wts[l] = w / S;
    }
    __syncthreads();

    // ---- out[e] = sum_{l<len} wts[l] * (keys[b][l][e] + pos[l][e]) ----
    {
        int e = tid & 127, half = tid >> 7;
        const float* kb = keys + (size_t)b * L_ * E_ + e;
        const float* pb = pos + e;
        int mid = (len + 1) >> 1;
        int l0 = half ? mid : 0;
        int l1 = half ? len : mid;
        float a0 = 0.f, a1 = 0.f, a2 = 0.f, a3 = 0.f;
        int l = l0;
        for (; l + 3 < l1; l += 4) {
            a0 = fmaf(m->wts[l],     __ldg(&kb[(size_t)l * E_])       + pb[(size_t)l * E_],       a0);
            a1 = fmaf(m->wts[l + 1], __ldg(&kb[(size_t)(l + 1) * E_]) + pb[(size_t)(l + 1) * E_], a1);
            a2 = fmaf(m->wts[l + 2], __ldg(&kb[(size_t)(l + 2) * E_]) + pb[(size_t)(l + 2) * E_], a2);
            a3 = fmaf(m->wts[l + 3], __ldg(&kb[(size_t)(l + 3) * E_]) + pb[(size_t)(l + 3) * E_], a3);
        }
        for (; l < l1; l++)
            a0 = fmaf(m->wts[l], __ldg(&kb[(size_t)l * E_]) + pb[(size_t)l * E_], a0);
        m->po[half * 128 + e] = (a0 + a1) + (a2 + a3);
    }
    __syncthreads();
    if (tid < 128)
        out[(size_t)b * E_ + tid] = m->po[tid] + m->po[128 + tid];
}

// ---------------- entry ----------------
extern "C" void kernel_launch(void* const* d_in, const int* in_sizes, int n_in,
                              void* d_out, int out_size) {
    const float* query = (const float*)d_in[0];
    const float* keys  = (const float*)d_in[1];
    const void*  klen  = d_in[2];
    const float* pos   = (const float*)d_in[3];
    const float* W1    = (const float*)d_in[4];
    const float* b1    = (const float*)d_in[5];
    const float* W2    = (const float*)d_in[6];
    const float* b2    = (const float*)d_in[7];
    const float* W3    = (const float*)d_in[8];
    const float* b3    = (const float*)d_in[9];
    float* out = (float*)d_out;
    (void)in_sizes; (void)n_in; (void)out_size;

    cudaFuncSetAttribute(din_main, cudaFuncAttributeMaxDynamicSharedMemorySize,
                         SMEM_TOTAL);
    cudaFuncSetAttribute(prep_qw2, cudaFuncAttributeMaxDynamicSharedMemorySize,
                         E_ * A_ * 4);

    prep_wt<<<(A_ * E_ + 255) / 256, 256>>>(W1, W2);
    prep_qw2<<<B_ / 32, 256, E_ * A_ * 4>>>(query, b1);
    din_main<<<B_, 256, SMEM_TOTAL>>>(query, keys, klen, pos, b2, W3, b3, out);
}